// round 12
// baseline (speedup 1.0000x reference)
#include <cuda_runtime.h>
#include <cuda_fp16.h>
#include <cstdint>
#include <math.h>

// ---------------------------------------------------------------------------
// Actor_Critic — single-pass fp16 MMA pipeline, LSTM fused into gates GEMM
// epilogue via gate-interleaved weights + lane-pair shuffle (no smem staging).
// 256-thread GEMM CTAs, K64 chunks, 3-stage cp.async ring, one barrier/chunk.
// ---------------------------------------------------------------------------

constexpr size_t S_B = 32768;

// fp32 scratch
constexpr size_t F_TAB   = 0;
constexpr size_t F_PRE2  = 1024;
constexpr size_t F_MLP   = 8192;
constexpr size_t F_QOUT  = F_MLP   + S_B * 512;
constexpr size_t F_PV2   = F_QOUT  + S_B * 256;      // [B,96]: pol2 0:64 | val2 64:96
constexpr size_t F_END   = F_PV2   + S_B * 96;
__device__ float g_f32[F_END];

// fp16 scratch
constexpr size_t H_WIH   = 0;                        // 1024x256 (gate-interleaved)
constexpr size_t H_WHH   = H_WIH   + 262144;         // 1024x256 (gate-interleaved)
constexpr size_t H_WBA   = H_WHH   + 262144;         // 512x512
constexpr size_t H_WQ    = H_WBA   + 262144;         // 256x256
constexpr size_t H_WK    = H_WQ    + 65536;          // 256x256
constexpr size_t H_WAT   = H_WK    + 65536;          // 256x512
constexpr size_t H_WPV   = H_WAT   + 131072;         // 192x256
constexpr size_t H_WC    = H_WPV   + 49152;          // 128x192 block-diag
constexpr size_t H_FUS   = H_WC    + 24576;          // B*256
constexpr size_t H_HXI   = H_FUS   + S_B * 256;
constexpr size_t H_QRY   = H_HXI   + S_B * 256;
constexpr size_t H_HXO   = H_QRY   + S_B * 256;
constexpr size_t H_MLP   = H_HXO   + S_B * 256;      // B*512
constexpr size_t H_AVEC  = H_MLP   + S_B * 512;
constexpr size_t H_ATT   = H_AVEC  + S_B * 256;
constexpr size_t H_P1V1  = H_ATT   + S_B * 256;      // B*192
constexpr size_t H_END   = H_P1V1  + S_B * 192;
__device__ __half g_hf[H_END];

__device__ __forceinline__ float sigmoidf_(float x) { return 1.f / (1.f + expf(-x)); }
__device__ __forceinline__ uint32_t pack2h(__half a, __half b) {
    return (uint32_t)__half_as_ushort(a) | ((uint32_t)__half_as_ushort(b) << 16);
}

// ---------------------------------------------------------------------------
// K0: gated_att table (4x256) + pre2 table (4x1024), pre2 GATE-PERMUTED:
// pre2[r][4u+g] = (b_ih + b_hh + gated_att @ w_ih[:,256:])[g*256+u]
// ---------------------------------------------------------------------------
__global__ void k0_tables(const float* __restrict__ emb,  const float* __restrict__ w_ta,
                          const float* __restrict__ b_ta, const float* __restrict__ w_ih,
                          const float* __restrict__ b_ih, const float* __restrict__ b_hh,
                          float* __restrict__ tab, float* __restrict__ pre2) {
    int t = threadIdx.x;  // 1024
    {
        int r = t >> 8, j = t & 255;
        float s = b_ta[j];
        #pragma unroll
        for (int k = 0; k < 25; k++) s += emb[r * 25 + k] * w_ta[j * 25 + k];
        tab[t] = sigmoidf_(s);
    }
    __syncthreads();
    {
        int u = t >> 2, g = t & 3;
        int j = g * 256 + u;                 // old row index
        const float* wrow = &w_ih[(size_t)j * 512 + 256];
        float base = b_ih[j] + b_hh[j];
        for (int r = 0; r < 4; r++) {
            const float* tr = &tab[r * 256];
            float s = base;
            for (int k = 0; k < 256; k++) s += tr[k] * wrow[k];
            pre2[r * 1024 + t] = s;          // permuted position
        }
    }
}

// ---------------------------------------------------------------------------
// fused weight convert to fp16.
// mode 0: normal; mode 2: p2/v2 block-diag; mode 3: gate-permute rows.
// ---------------------------------------------------------------------------
struct WSeg { const float* src; const float* src2; int srcld, cols, rows, total, mode;
              long long hoff; };
struct WAll { WSeg s[9]; };

__global__ void k_wsplit_all(WAll d, __half* __restrict__ base) {
    int i = blockIdx.x * blockDim.x + threadIdx.x;
    #pragma unroll
    for (int s = 0; s < 9; s++) {
        const WSeg& g = d.s[s];
        if (i < g.total) {
            float v;
            if (g.mode == 0) {
                int r = i / g.cols, c = i - r * g.cols;
                v = (r < g.rows) ? g.src[(size_t)r * g.srcld + c] : 0.f;
            } else if (g.mode == 3) {
                int r = i / g.cols, c = i - r * g.cols;
                int orow = (r & 3) * 256 + (r >> 2);   // gate-interleave
                v = g.src[(size_t)orow * g.srcld + c];
            } else {
                int r = i / 192, c = i - r * 192;
                if (r < 64)       v = (c < 128) ? g.src[r * 128 + c] : 0.f;
                else if (c >= 128 && r - 64 < 32) v = g.src2[(r - 64) * 64 + (c - 128)];
                else              v = 0.f;
            }
            base[g.hoff + i] = __float2half(v);
            return;
        }
        i -= g.total;
    }
}

// ---------------------------------------------------------------------------
// fused prep: region 0 fusion(img*tab[idx]); 1: round hx_in; 2: round query
// ---------------------------------------------------------------------------
__global__ void k_prep(const float4* __restrict__ img, const int* __restrict__ idx,
                       const float* __restrict__ tab,
                       const float4* __restrict__ hx_in, const float4* __restrict__ query,
                       __half* __restrict__ fus, __half* __restrict__ hxi,
                       __half* __restrict__ qry, int nq) {
    int i = blockIdx.x * blockDim.x + threadIdx.x;
    int reg = 0;
    if (i >= nq) { i -= nq; reg = 1; }
    if (i >= nq) { i -= nq; reg = 2; }
    if (i >= nq) return;
    float4 v;
    __half* dst;
    if (reg == 0) {
        int b = i >> 6, j4 = (i & 63) << 2;
        float4 g = *reinterpret_cast<const float4*>(tab + idx[b] * 256 + j4);
        v = img[i];
        v.x *= g.x; v.y *= g.y; v.z *= g.z; v.w *= g.w;
        dst = fus;
    } else if (reg == 1) { v = hx_in[i]; dst = hxi; }
    else                 { v = query[i]; dst = qry; }
    uint2 u = make_uint2(pack2h(__float2half(v.x), __float2half(v.y)),
                         pack2h(__float2half(v.z), __float2half(v.w)));
    *reinterpret_cast<uint2*>(dst + (size_t)i * 4) = u;
}

// ---------------------------------------------------------------------------
// MMA / cp.async helpers
// ---------------------------------------------------------------------------
__device__ __forceinline__ void ldm4(uint32_t* r, uint32_t addr) {
    asm volatile("ldmatrix.sync.aligned.m8n8.x4.shared.b16 {%0,%1,%2,%3}, [%4];"
                 : "=r"(r[0]), "=r"(r[1]), "=r"(r[2]), "=r"(r[3]) : "r"(addr));
}
__device__ __forceinline__ void mma16816(float* c, const uint32_t* a, uint32_t b0, uint32_t b1) {
    asm volatile(
        "mma.sync.aligned.m16n8k16.row.col.f32.f16.f16.f32 "
        "{%0,%1,%2,%3}, {%4,%5,%6,%7}, {%8,%9}, {%0,%1,%2,%3};"
        : "+f"(c[0]), "+f"(c[1]), "+f"(c[2]), "+f"(c[3])
        : "r"(a[0]), "r"(a[1]), "r"(a[2]), "r"(a[3]), "r"(b0), "r"(b1));
}
#define CPA16(dst, src) asm volatile("cp.async.cg.shared.global [%0], [%1], 16;\n" :: "r"(dst), "l"(src))
#define CPCOMMIT()      asm volatile("cp.async.commit_group;\n")
#define CPWAIT1()       asm volatile("cp.async.wait_group 1;\n")
#define CPWAIT0()       asm volatile("cp.async.wait_group 0;\n")

// ---------------------------------------------------------------------------
// GEMM: C = epi( sum_seg A_seg @ W_seg^T ), fp16 single pass, fp32 acc.
// 256 threads, 8 warps (4m x 2n), BM=128, K64 chunks (144B rows), 3-stage
// cp.async ring, one barrier/chunk. 2 CTAs/SM.
// EPI 0: +bias (split at nsplit into bias/bias2), relu if ACT
// EPI 2: (+bias, relu) -> tanh(aux0[m*256+n]+v) * aux1[m*512+256+n]
// EPI 3: fused LSTM, gate-interleaved cols: +aux0[idxp[m]*1024+n] (pre2),
//        lane-pair shuffle assembles (i,f,g,o); writes C=hx_f32, C2=cx_f32,
//        Ch=hx_f16; aux1 = cx_in. (gates GEMM: N=1024, BN=128.)
// OUTM bit0: fp32 C; bit1: fp16 Ch.
// ---------------------------------------------------------------------------
template <int BN, int ACT, int EPI, int OUTM>
__global__ void __launch_bounds__(256, 2)
mma_gemm(int N,
         const __half* __restrict__ A0, int lda0,
         const __half* __restrict__ W0, int ldw0, int K0,
         const __half* __restrict__ A1, int lda1,
         const __half* __restrict__ W1, int ldw1, int K1,
         const float* __restrict__ bias, const float* __restrict__ bias2, int nsplit,
         const float* __restrict__ aux0, const float* __restrict__ aux1,
         const int* __restrict__ idxp,
         float* __restrict__ C, float* __restrict__ C2,
         __half* __restrict__ Ch, int ldc) {
    constexpr int WN      = BN / 2;                 // warp n-extent (2 warps in n)
    constexpr int NT8     = WN / 8;
    constexpr int N16T    = WN / 16;
    constexpr int SSTR    = 72;                     // halves/row: 64 data + 8 pad (144B)
    constexpr int A_BYTES = 128 * SSTR * 2;         // 18432
    constexpr int W_BYTES = BN * SSTR * 2;
    constexpr int STAGEB  = A_BYTES + W_BYTES;
    constexpr int WIT     = BN / 32;                // W cp.async iters

    extern __shared__ __half smem_dyn[];

    const int tid  = threadIdx.x;
    const int lane = tid & 31;
    const int wid  = tid >> 5;
    const int wm = wid & 3, wn = wid >> 2;          // 4 x 2 warps
    const int m0 = blockIdx.y * 128;
    const int n0 = blockIdx.x * BN;

    const uint32_t smb = (uint32_t)__cvta_generic_to_shared(smem_dyn);

    float acc[2][NT8][4];
    #pragma unroll
    for (int i = 0; i < 2; i++)
        #pragma unroll
        for (int j = 0; j < NT8; j++)
            #pragma unroll
            for (int q = 0; q < 4; q++) acc[i][j][q] = 0.f;

    const int nc0 = K0 >> 6;
    const int NC  = nc0 + (K1 >> 6);

    auto issue = [&](int c) {
        const __half *A, *W;
        int lda, ldw, kc;
        if (c < nc0) { A = A0; W = W0; lda = lda0; ldw = ldw0; kc = c << 6; }
        else         { A = A1; W = W1; lda = lda1; ldw = ldw1; kc = (c - nc0) << 6; }
        const uint32_t sb = smb + (uint32_t)(c % 3) * STAGEB;
        #pragma unroll
        for (int it = 0; it < 4; it++) {            // A: 128 rows x 8 segs
            int idx = tid + it * 256;
            int row = idx >> 3, seg = idx & 7;
            uint32_t off = (uint32_t)(row * SSTR + seg * 8) * 2;
            CPA16(sb + off, A + (size_t)(m0 + row) * lda + kc + seg * 8);
        }
        #pragma unroll
        for (int it = 0; it < WIT; it++) {          // W: BN rows x 8 segs
            int idx = tid + it * 256;
            int row = idx >> 3, seg = idx & 7;
            uint32_t off = (uint32_t)(row * SSTR + seg * 8) * 2;
            CPA16(sb + A_BYTES + off, W + (size_t)(n0 + row) * ldw + kc + seg * 8);
        }
    };

    issue(0); CPCOMMIT();
    if (NC > 1) { issue(1); CPCOMMIT(); }

    for (int c = 0; c < NC; c++) {
        if (c + 1 < NC) CPWAIT1(); else CPWAIT0();  // stage c landed
        __syncthreads();                            // also: all warps done with c-1
        if (c + 2 < NC) { issue(c + 2); CPCOMMIT(); }  // overwrites stage of c-1: safe

        const uint32_t sb = smb + (uint32_t)(c % 3) * STAGEB;
        const uint32_t bA = sb;
        const uint32_t bW = sb + A_BYTES;

        #pragma unroll
        for (int kk = 0; kk < 64; kk += 16) {
            const int col = kk + ((lane >> 4) << 3);
            uint32_t a0[4], a1[4];
            {
                int row = wm * 32 + (lane & 15);
                ldm4(a0, bA + (uint32_t)(row * SSTR + col) * 2u);
                ldm4(a1, bA + (uint32_t)((row + 16) * SSTR + col) * 2u);
            }
            #pragma unroll
            for (int t = 0; t < N16T; t++) {
                uint32_t bh[4];
                int row = wn * WN + t * 16 + (lane & 15);
                ldm4(bh, bW + (uint32_t)(row * SSTR + col) * 2u);
                #pragma unroll
                for (int hs = 0; hs < 2; hs++) {
                    int nt = 2 * t + hs;
                    mma16816(acc[0][nt], a0, bh[hs], bh[2 + hs]);
                    mma16816(acc[1][nt], a1, bh[hs], bh[2 + hs]);
                }
            }
        }
    }

    if (EPI == 3) {
        // ---- fused LSTM epilogue: lane-pair shuffle, no smem, no barriers ----
        // thread at cols cc(=4u+{0,1} or 4u+{2,3}), partner lane^1 holds the
        // other half of unit u. Even lanes (cc&3==0) compute and store.
        #pragma unroll
        for (int mt = 0; mt < 2; mt++) {
            int r0 = m0 + wm * 32 + mt * 16 + (lane >> 2);
            int ib0 = idxp[r0];
            int ib1 = idxp[r0 + 8];
            #pragma unroll
            for (int nt = 0; nt < NT8; nt++) {
                int cc = n0 + wn * WN + nt * 8 + ((lane & 3) << 1);
                #pragma unroll
                for (int p = 0; p < 2; p++) {
                    int r  = p ? (r0 + 8) : r0;
                    int ib = p ? ib1 : ib0;
                    float x = acc[mt][nt][2 * p]     + aux0[(size_t)ib * 1024 + cc];
                    float y = acc[mt][nt][2 * p + 1] + aux0[(size_t)ib * 1024 + cc + 1];
                    float px = __shfl_xor_sync(0xffffffffu, x, 1);
                    float py = __shfl_xor_sync(0xffffffffu, y, 1);
                    if ((lane & 1) == 0) {
                        int U = cc >> 2;
                        size_t o = (size_t)r * 256 + U;
                        float ii = sigmoidf_(x),  ff = sigmoidf_(y);
                        float gg = tanhf(px),     oo = sigmoidf_(py);
                        float c2 = ff * aux1[o] + ii * gg;   // aux1 = cx_in
                        float hh = oo * tanhf(c2);
                        C[o]  = hh;
                        C2[o] = c2;
                        Ch[o] = __float2half(hh);
                    }
                }
            }
        }
        return;
    }

    // ---- standard epilogue ----
    #pragma unroll
    for (int mt = 0; mt < 2; mt++) {
        int r0 = m0 + wm * 32 + mt * 16 + (lane >> 2);
        int r1 = r0 + 8;
        #pragma unroll
        for (int nt = 0; nt < NT8; nt++) {
            int cc = n0 + wn * WN + nt * 8 + ((lane & 3) << 1);
            if (cc < N) {
                float bb0 = 0.f, bb1 = 0.f;
                if (bias) {
                    if (cc < nsplit) { bb0 = bias[cc]; bb1 = bias[cc + 1]; }
                    else             { bb0 = bias2[cc - nsplit]; bb1 = bias2[cc + 1 - nsplit]; }
                }
                #pragma unroll
                for (int p = 0; p < 2; p++) {
                    int r = p ? r1 : r0;
                    float x = acc[mt][nt][2 * p] + bb0;
                    float y = acc[mt][nt][2 * p + 1] + bb1;
                    if (ACT) { x = fmaxf(x, 0.f); y = fmaxf(y, 0.f); }
                    if (EPI == 2) {
                        x = tanhf(aux0[(size_t)r * 256 + cc] + x)     * aux1[(size_t)r * 512 + 256 + cc];
                        y = tanhf(aux0[(size_t)r * 256 + cc + 1] + y) * aux1[(size_t)r * 512 + 256 + cc + 1];
                    }
                    size_t o = (size_t)r * ldc + cc;
                    if (OUTM & 1)
                        *reinterpret_cast<float2*>(&C[o]) = make_float2(x, y);
                    if (OUTM & 2)
                        *reinterpret_cast<uint32_t*>(Ch + o) = pack2h(__float2half(x), __float2half(y));
                }
            }
        }
    }
}

// ---------------------------------------------------------------------------
// Final heads: pv2 [B,96] = pol2(0:64) | val2(64:96)
// ---------------------------------------------------------------------------
__global__ void k_heads(const float* __restrict__ pv2,
                        const float* __restrict__ w_p, const float* __restrict__ b_p,
                        const float* __restrict__ w_v, const float* __restrict__ b_v,
                        float* __restrict__ out_val, float* __restrict__ out_pol) {
    __shared__ float sp[64][97];
    int r0 = blockIdx.x * 64;
    for (int i = threadIdx.x; i < 64 * 96; i += blockDim.x) {
        int r = i / 96, c = i - r * 96;
        sp[r][c] = pv2[(size_t)(r0 + r) * 96 + c];
    }
    __syncthreads();
    int t = threadIdx.x;
    if (t < 64) {
        int b = r0 + t;
        float p0 = b_p[0], p1 = b_p[1], p2 = b_p[2];
        #pragma unroll
        for (int k = 0; k < 64; k++) {
            float x = sp[t][k];
            p0 = fmaf(x, w_p[k], p0);
            p1 = fmaf(x, w_p[64 + k], p1);
            p2 = fmaf(x, w_p[128 + k], p2);
        }
        out_pol[(size_t)b * 3 + 0] = p0;
        out_pol[(size_t)b * 3 + 1] = p1;
        out_pol[(size_t)b * 3 + 2] = p2;
        float v = b_v[0];
        #pragma unroll
        for (int k = 0; k < 32; k++) v = fmaf(sp[t][64 + k], w_v[k], v);
        out_val[b] = v;
    }
}

// ---------------------------------------------------------------------------
// host launcher
// ---------------------------------------------------------------------------
extern "C" void kernel_launch(void* const* d_in, const int* in_sizes, int n_in,
                              void* d_out, int out_size) {
    const float* img   = (const float*)d_in[0];
    const int*   idx   = (const int*)  d_in[1];
    const float* hx_in = (const float*)d_in[2];
    const float* cx_in = (const float*)d_in[3];
    const float* query = (const float*)d_in[4];
    const float* emb   = (const float*)d_in[5];
    const float* w_ta  = (const float*)d_in[6];
    const float* b_ta  = (const float*)d_in[7];
    const float* w_ih  = (const float*)d_in[8];
    const float* w_hh  = (const float*)d_in[9];
    const float* b_ih  = (const float*)d_in[10];
    const float* b_hh  = (const float*)d_in[11];
    const float* w_q   = (const float*)d_in[12];
    const float* b_q   = (const float*)d_in[13];
    const float* w_k   = (const float*)d_in[14];
    const float* b_k   = (const float*)d_in[15];
    const float* w_ba  = (const float*)d_in[16];
    const float* b_ba  = (const float*)d_in[17];
    const float* w_at  = (const float*)d_in[18];
    const float* b_at  = (const float*)d_in[19];
    const float* w_p1  = (const float*)d_in[20];
    const float* b_p1  = (const float*)d_in[21];
    const float* w_p2  = (const float*)d_in[22];
    const float* b_p2  = (const float*)d_in[23];
    const float* w_p   = (const float*)d_in[24];
    const float* b_p   = (const float*)d_in[25];
    const float* w_v1  = (const float*)d_in[26];
    const float* b_v1  = (const float*)d_in[27];
    const float* w_v2  = (const float*)d_in[28];
    const float* b_v2  = (const float*)d_in[29];
    const float* w_v   = (const float*)d_in[30];
    const float* b_v   = (const float*)d_in[31];

    const int B = in_sizes[0] / 256;  // 32768

    float* F = nullptr;
    cudaGetSymbolAddress((void**)&F, g_f32);
    __half* HF = nullptr;
    cudaGetSymbolAddress((void**)&HF, g_hf);

    float* tab   = F + F_TAB;
    float* pre2  = F + F_PRE2;
    float* mlpf  = F + F_MLP;
    float* qout  = F + F_QOUT;
    float* pv2   = F + F_PV2;

    float* out   = (float*)d_out;
    float* o_val = out;
    float* o_pol = out + (size_t)B;
    float* o_hx  = out + (size_t)B * 4;
    float* o_cx  = o_hx + (size_t)B * 256;

    // smem: 3 stages; stage = 18432 + BN*144
    const int SM128 = 3 * (18432 + 128 * 144);  // 110592
    const int SM64  = 3 * (18432 + 64 * 144);   // 82944
    cudaFuncSetAttribute(mma_gemm<128, 0, 3, 0>, cudaFuncAttributeMaxDynamicSharedMemorySize, SM128);
    cudaFuncSetAttribute(mma_gemm<128, 1, 0, 1>, cudaFuncAttributeMaxDynamicSharedMemorySize, SM128);
    cudaFuncSetAttribute(mma_gemm<128, 1, 0, 3>, cudaFuncAttributeMaxDynamicSharedMemorySize, SM128);
    cudaFuncSetAttribute(mma_gemm<128, 1, 2, 2>, cudaFuncAttributeMaxDynamicSharedMemorySize, SM128);
    cudaFuncSetAttribute(mma_gemm<128, 1, 0, 2>, cudaFuncAttributeMaxDynamicSharedMemorySize, SM128);
    cudaFuncSetAttribute(mma_gemm<64, 1, 0, 2>,  cudaFuncAttributeMaxDynamicSharedMemorySize, SM64);
    cudaFuncSetAttribute(mma_gemm<64, 1, 0, 1>,  cudaFuncAttributeMaxDynamicSharedMemorySize, SM64);

    // K0: tables (pre2 gate-permuted)
    k0_tables<<<1, 1024>>>(emb, w_ta, b_ta, w_ih, b_ih, b_hh, tab, pre2);

    // fused weight convert (9 segments, one launch)
    {
        WAll d;
        auto seg = [&](int i, const float* src, int srcld, int cols, int rows, int padrows,
                       size_t hoff, int mode) {
            d.s[i] = WSeg{src, nullptr, srcld, cols, rows, padrows * cols, mode, (long long)hoff};
        };
        seg(0, w_ih, 512, 256, 1024, 1024, H_WIH, 3);   // gate-interleaved
        seg(1, w_hh, 256, 256, 1024, 1024, H_WHH, 3);   // gate-interleaved
        seg(2, w_ba, 512, 512, 512, 512, H_WBA, 0);
        seg(3, w_q,  256, 256, 256, 256, H_WQ, 0);
        seg(4, w_k,  256, 256, 256, 256, H_WK, 0);
        seg(5, w_at, 512, 512, 256, 256, H_WAT, 0);
        seg(6, w_p1, 256, 256, 128, 128, H_WPV, 0);
        seg(7, w_v1, 256, 256, 64, 64, H_WPV + 128 * 256, 0);
        d.s[8] = WSeg{w_p2, w_v2, 0, 0, 0, 128 * 192, 2, (long long)H_WC};
        int total = 0;
        for (int i = 0; i < 9; i++) total += d.s[i].total;
        k_wsplit_all<<<(total + 255) / 256, 256>>>(d, HF);
    }

    // fused prep
    k_prep<<<(3 * B * 64 + 255) / 256, 256>>>(
        (const float4*)img, idx, tab, (const float4*)hx_in, (const float4*)query,
        HF + H_FUS, HF + H_HXI, HF + H_QRY, B * 64);

    // K2: gates GEMM + fused LSTM -> o_hx, o_cx, hx fp16 (gate-interleaved W)
    mma_gemm<128, 0, 3, 0><<<dim3(8, B / 128), 256, SM128>>>(
        1024,
        HF + H_FUS, 256, HF + H_WIH, 256, 256,
        HF + H_HXI, 256, HF + H_WHH, 256, 256,
        nullptr, nullptr, 1 << 30, pre2, cx_in, idx,
        o_hx, o_cx, HF + H_HXO, 256);

    // K5: qout = relu(query @ w_q^T + b_q)  (fp32)
    mma_gemm<128, 1, 0, 1><<<dim3(2, B / 128), 256, SM128>>>(
        256,
        HF + H_QRY, 256, HF + H_WQ, 256, 256,
        nullptr, 0, nullptr, 0, 0,
        b_q, nullptr, 1 << 30, nullptr, nullptr, nullptr, qout, nullptr, nullptr, 256);

    // K4: mlp = relu([fus|hx] @ w_ba^T + b_ba)  (fp32 + fp16)
    mma_gemm<128, 1, 0, 3><<<dim3(4, B / 128), 256, SM128>>>(
        512,
        HF + H_FUS, 256, HF + H_WBA, 512, 256,
        HF + H_HXO, 256, HF + H_WBA + 256, 512, 256,
        b_ba, nullptr, 1 << 30, nullptr, nullptr, nullptr, mlpf, nullptr, HF + H_MLP, 512);

    // K6: avec = tanh(qout + relu(key @ w_k^T + b_k)) * val  (fp16)
    mma_gemm<128, 1, 2, 2><<<dim3(2, B / 128), 256, SM128>>>(
        256,
        HF + H_MLP, 512, HF + H_WK, 256, 256,
        nullptr, 0, nullptr, 0, 0,
        b_k, nullptr, 1 << 30, qout, mlpf, nullptr, nullptr, nullptr, HF + H_AVEC, 256);

    // K7: attnw = relu([avec|hx] @ w_at^T + b_at)  (fp16)
    mma_gemm<128, 1, 0, 2><<<dim3(2, B / 128), 256, SM128>>>(
        256,
        HF + H_AVEC, 256, HF + H_WAT, 512, 256,
        HF + H_HXO, 256, HF + H_WAT + 256, 512, 256,
        b_at, nullptr, 1 << 30, nullptr, nullptr, nullptr, nullptr, nullptr, HF + H_ATT, 256);

    // K8: [pol1|val1] = relu(attnw @ [w_p1;w_v1]^T + [b_p1;b_v1])  N=192 (fp16)
    mma_gemm<64, 1, 0, 2><<<dim3(3, B / 128), 256, SM64>>>(
        192,
        HF + H_ATT, 256, HF + H_WPV, 256, 256,
        nullptr, 0, nullptr, 0, 0,
        b_p1, b_v1, 128, nullptr, nullptr, nullptr, nullptr, nullptr, HF + H_P1V1, 192);

    // K9: [pol2|val2] = relu([pol1|val1] @ blockdiag(w_p2,w_v2)^T + [b_p2;b_v2])  N=96 (fp32)
    mma_gemm<64, 1, 0, 1><<<dim3(2, B / 128), 256, SM64>>>(
        96,
        HF + H_P1V1, 192, HF + H_WC, 192, 192,
        nullptr, 0, nullptr, 0, 0,
        b_p2, b_v2, 64, nullptr, nullptr, nullptr, pv2, nullptr, nullptr, 96);

    // K10: heads
    k_heads<<<B / 64, 256>>>(pv2, w_p, b_p, w_v, b_v, o_val, o_pol);
}

// round 13
// speedup vs baseline: 1.0980x; 1.0980x over previous
#include <cuda_runtime.h>
#include <cuda_fp16.h>
#include <cstdint>
#include <math.h>

// ---------------------------------------------------------------------------
// Actor_Critic — single-pass fp16 MMA pipeline (round-10 architecture).
// 256-thread GEMM CTAs, K64 chunks, 3-stage cp.async ring, one barrier/chunk,
// 2 CTAs/SM. qout GEMM merged into the gates launch as extra grid slices.
// ---------------------------------------------------------------------------

constexpr size_t S_B = 32768;

// fp32 scratch
constexpr size_t F_TAB   = 0;
constexpr size_t F_PRE2  = 1024;
constexpr size_t F_GATES = 8192;
constexpr size_t F_MLP   = F_GATES + S_B * 1024;
constexpr size_t F_QOUT  = F_MLP   + S_B * 512;
constexpr size_t F_PV2   = F_QOUT  + S_B * 256;      // [B,96]: pol2 0:64 | val2 64:96
constexpr size_t F_END   = F_PV2   + S_B * 96;
__device__ float g_f32[F_END];

// fp16 scratch
constexpr size_t H_WIH   = 0;                        // 1024x256
constexpr size_t H_WHH   = H_WIH   + 262144;         // 1024x256
constexpr size_t H_WBA   = H_WHH   + 262144;         // 512x512
constexpr size_t H_WQ    = H_WBA   + 262144;         // 256x256
constexpr size_t H_WK    = H_WQ    + 65536;          // 256x256
constexpr size_t H_WAT   = H_WK    + 65536;          // 256x512
constexpr size_t H_WPV   = H_WAT   + 131072;         // 192x256
constexpr size_t H_WC    = H_WPV   + 49152;          // 128x192 block-diag
constexpr size_t H_FUS   = H_WC    + 24576;          // B*256
constexpr size_t H_HXI   = H_FUS   + S_B * 256;
constexpr size_t H_QRY   = H_HXI   + S_B * 256;
constexpr size_t H_HXO   = H_QRY   + S_B * 256;
constexpr size_t H_MLP   = H_HXO   + S_B * 256;      // B*512
constexpr size_t H_AVEC  = H_MLP   + S_B * 512;
constexpr size_t H_ATT   = H_AVEC  + S_B * 256;
constexpr size_t H_P1V1  = H_ATT   + S_B * 256;      // B*192
constexpr size_t H_END   = H_P1V1  + S_B * 192;
__device__ __half g_hf[H_END];

__device__ __forceinline__ float sigmoidf_(float x) { return 1.f / (1.f + expf(-x)); }
__device__ __forceinline__ uint32_t pack2h(__half a, __half b) {
    return (uint32_t)__half_as_ushort(a) | ((uint32_t)__half_as_ushort(b) << 16);
}

// ---------------------------------------------------------------------------
// K0: gated_att table (4x256) + pre2 table (4x1024)
// ---------------------------------------------------------------------------
__global__ void k0_tables(const float* __restrict__ emb,  const float* __restrict__ w_ta,
                          const float* __restrict__ b_ta, const float* __restrict__ w_ih,
                          const float* __restrict__ b_ih, const float* __restrict__ b_hh,
                          float* __restrict__ tab, float* __restrict__ pre2) {
    int t = threadIdx.x;  // 1024
    {
        int r = t >> 8, j = t & 255;
        float s = b_ta[j];
        #pragma unroll
        for (int k = 0; k < 25; k++) s += emb[r * 25 + k] * w_ta[j * 25 + k];
        tab[t] = sigmoidf_(s);
    }
    __syncthreads();
    {
        int j = t;
        const float* wrow = &w_ih[(size_t)j * 512 + 256];
        float base = b_ih[j] + b_hh[j];
        for (int r = 0; r < 4; r++) {
            const float* tr = &tab[r * 256];
            float s = base;
            for (int k = 0; k < 256; k++) s += tr[k] * wrow[k];
            pre2[r * 1024 + j] = s;
        }
    }
}

// ---------------------------------------------------------------------------
// fused weight convert to fp16. mode 0: normal; mode 2: p2/v2 block-diag.
// ---------------------------------------------------------------------------
struct WSeg { const float* src; const float* src2; int srcld, cols, rows, total, mode;
              long long hoff; };
struct WAll { WSeg s[9]; };

__global__ void k_wsplit_all(WAll d, __half* __restrict__ base) {
    int i = blockIdx.x * blockDim.x + threadIdx.x;
    #pragma unroll
    for (int s = 0; s < 9; s++) {
        const WSeg& g = d.s[s];
        if (i < g.total) {
            float v;
            if (g.mode == 0) {
                int r = i / g.cols, c = i - r * g.cols;
                v = (r < g.rows) ? g.src[(size_t)r * g.srcld + c] : 0.f;
            } else {
                int r = i / 192, c = i - r * 192;
                if (r < 64)       v = (c < 128) ? g.src[r * 128 + c] : 0.f;
                else if (c >= 128 && r - 64 < 32) v = g.src2[(r - 64) * 64 + (c - 128)];
                else              v = 0.f;
            }
            base[g.hoff + i] = __float2half(v);
            return;
        }
        i -= g.total;
    }
}

// ---------------------------------------------------------------------------
// fused prep: region 0 fusion(img*tab[idx]); 1: round hx_in; 2: round query
// ---------------------------------------------------------------------------
__global__ void k_prep(const float4* __restrict__ img, const int* __restrict__ idx,
                       const float* __restrict__ tab,
                       const float4* __restrict__ hx_in, const float4* __restrict__ query,
                       __half* __restrict__ fus, __half* __restrict__ hxi,
                       __half* __restrict__ qry, int nq) {
    int i = blockIdx.x * blockDim.x + threadIdx.x;
    int reg = 0;
    if (i >= nq) { i -= nq; reg = 1; }
    if (i >= nq) { i -= nq; reg = 2; }
    if (i >= nq) return;
    float4 v;
    __half* dst;
    if (reg == 0) {
        int b = i >> 6, j4 = (i & 63) << 2;
        float4 g = *reinterpret_cast<const float4*>(tab + idx[b] * 256 + j4);
        v = img[i];
        v.x *= g.x; v.y *= g.y; v.z *= g.z; v.w *= g.w;
        dst = fus;
    } else if (reg == 1) { v = hx_in[i]; dst = hxi; }
    else                 { v = query[i]; dst = qry; }
    uint2 u = make_uint2(pack2h(__float2half(v.x), __float2half(v.y)),
                         pack2h(__float2half(v.z), __float2half(v.w)));
    *reinterpret_cast<uint2*>(dst + (size_t)i * 4) = u;
}

// ---------------------------------------------------------------------------
// K3: LSTM -> hx,cx fp32 (outputs) + hx fp16
// ---------------------------------------------------------------------------
__global__ void k_lstm(const float* __restrict__ gates, const float* __restrict__ cx_in,
                       float* __restrict__ hx_out, float* __restrict__ cx_out,
                       __half* __restrict__ hxo, int totalq) {
    int i = blockIdx.x * blockDim.x + threadIdx.x;
    if (i >= totalq) return;
    int b = i >> 6, j = (i & 63) << 2;
    const float* g = gates + (size_t)b * 1024 + j;
    float4 gi = *reinterpret_cast<const float4*>(g);
    float4 gf = *reinterpret_cast<const float4*>(g + 256);
    float4 gg = *reinterpret_cast<const float4*>(g + 512);
    float4 go = *reinterpret_cast<const float4*>(g + 768);
    float4 c0 = *reinterpret_cast<const float4*>(cx_in + (size_t)b * 256 + j);
    float4 ho, co;
    co.x = sigmoidf_(gf.x) * c0.x + sigmoidf_(gi.x) * tanhf(gg.x); ho.x = sigmoidf_(go.x) * tanhf(co.x);
    co.y = sigmoidf_(gf.y) * c0.y + sigmoidf_(gi.y) * tanhf(gg.y); ho.y = sigmoidf_(go.y) * tanhf(co.y);
    co.z = sigmoidf_(gf.z) * c0.z + sigmoidf_(gi.z) * tanhf(gg.z); ho.z = sigmoidf_(go.z) * tanhf(co.z);
    co.w = sigmoidf_(gf.w) * c0.w + sigmoidf_(gi.w) * tanhf(gg.w); ho.w = sigmoidf_(go.w) * tanhf(co.w);
    size_t o = (size_t)b * 256 + j;
    *reinterpret_cast<float4*>(hx_out + o) = ho;
    *reinterpret_cast<float4*>(cx_out + o) = co;
    uint2 u = make_uint2(pack2h(__float2half(ho.x), __float2half(ho.y)),
                         pack2h(__float2half(ho.z), __float2half(ho.w)));
    *reinterpret_cast<uint2*>(hxo + o) = u;
}

// ---------------------------------------------------------------------------
// MMA / cp.async helpers
// ---------------------------------------------------------------------------
__device__ __forceinline__ void ldm4(uint32_t* r, uint32_t addr) {
    asm volatile("ldmatrix.sync.aligned.m8n8.x4.shared.b16 {%0,%1,%2,%3}, [%4];"
                 : "=r"(r[0]), "=r"(r[1]), "=r"(r[2]), "=r"(r[3]) : "r"(addr));
}
__device__ __forceinline__ void mma16816(float* c, const uint32_t* a, uint32_t b0, uint32_t b1) {
    asm volatile(
        "mma.sync.aligned.m16n8k16.row.col.f32.f16.f16.f32 "
        "{%0,%1,%2,%3}, {%4,%5,%6,%7}, {%8,%9}, {%0,%1,%2,%3};"
        : "+f"(c[0]), "+f"(c[1]), "+f"(c[2]), "+f"(c[3])
        : "r"(a[0]), "r"(a[1]), "r"(a[2]), "r"(a[3]), "r"(b0), "r"(b1));
}
#define CPA16(dst, src) asm volatile("cp.async.cg.shared.global [%0], [%1], 16;\n" :: "r"(dst), "l"(src))
#define CPCOMMIT()      asm volatile("cp.async.commit_group;\n")
#define CPWAIT1()       asm volatile("cp.async.wait_group 1;\n")
#define CPWAIT0()       asm volatile("cp.async.wait_group 0;\n")

// ---------------------------------------------------------------------------
// GEMM: C = epi( sum_seg A_seg @ W_seg^T ), fp16 single pass, fp32 acc.
// 256 threads, 8 warps (4m x 2n), BM=128, K64 chunks (144B rows), 3-stage
// cp.async ring, one barrier/chunk. 2 CTAs/SM.
// EPI 0: +bias (split at nsplit into bias/bias2), relu if ACT
// EPI 1: +aux0[idxp[m]*1024+n]
// EPI 2: (+bias, relu) -> tanh(aux0[m*256+n]+v) * aux1[m*512+256+n]
// EPI 5: dual-job (gates + qout): blockIdx.x < gx1 -> gates (EPI1 semantics,
//        N=1024, writes C); else qout job (A=Aq,W=Wq,K=Kq, +biasq, relu,
//        writes Cq, N=256).
// OUTM bit0: fp32 C always; bit2: fp32 C only for cc>=256; bit1: fp16 Ch.
// ---------------------------------------------------------------------------
template <int BN, int ACT, int EPI, int OUTM>
__global__ void __launch_bounds__(256, 2)
mma_gemm(int N,
         const __half* __restrict__ A0, int lda0,
         const __half* __restrict__ W0, int ldw0, int K0,
         const __half* __restrict__ A1, int lda1,
         const __half* __restrict__ W1, int ldw1, int K1,
         const float* __restrict__ bias, const float* __restrict__ bias2, int nsplit,
         const float* __restrict__ aux0, const float* __restrict__ aux1,
         const int* __restrict__ idxp,
         float* __restrict__ C, __half* __restrict__ Ch, int ldc,
         const __half* __restrict__ Aq, int ldaq,
         const __half* __restrict__ Wq, int ldwq, int Kq,
         const float* __restrict__ biasq, float* __restrict__ Cq, int ldcq, int gx1) {
    constexpr int WN      = BN / 2;                 // warp n-extent (2 warps in n)
    constexpr int NT8     = WN / 8;
    constexpr int N16T    = WN / 16;
    constexpr int SSTR    = 72;                     // halves/row: 64 data + 8 pad (144B)
    constexpr int A_BYTES = 128 * SSTR * 2;         // 18432
    constexpr int W_BYTES = BN * SSTR * 2;
    constexpr int STAGEB  = A_BYTES + W_BYTES;
    constexpr int WIT     = BN / 32;                // W cp.async iters

    extern __shared__ __half smem_dyn[];

    const int tid  = threadIdx.x;
    const int lane = tid & 31;
    const int wid  = tid >> 5;
    const int wm = wid & 3, wn = wid >> 2;          // 4 x 2 warps
    const int m0 = blockIdx.y * 128;

    const bool isq = (EPI == 5) && ((int)blockIdx.x >= gx1);
    const int n0 = (isq ? ((int)blockIdx.x - gx1) : (int)blockIdx.x) * BN;

    // job-selected operand streams
    const __half* jA0 = isq ? Aq : A0;  const int jlda0 = isq ? ldaq : lda0;
    const __half* jW0 = isq ? Wq : W0;  const int jldw0 = isq ? ldwq : ldw0;
    const int jK0 = isq ? Kq : K0;
    const int jK1 = isq ? 0  : K1;

    const uint32_t smb = (uint32_t)__cvta_generic_to_shared(smem_dyn);

    float acc[2][NT8][4];
    #pragma unroll
    for (int i = 0; i < 2; i++)
        #pragma unroll
        for (int j = 0; j < NT8; j++)
            #pragma unroll
            for (int q = 0; q < 4; q++) acc[i][j][q] = 0.f;

    const int nc0 = jK0 >> 6;
    const int NC  = nc0 + (jK1 >> 6);

    auto issue = [&](int c) {
        const __half *A, *W;
        int lda, ldw, kc;
        if (c < nc0) { A = jA0; W = jW0; lda = jlda0; ldw = jldw0; kc = c << 6; }
        else         { A = A1;  W = W1;  lda = lda1;  ldw = ldw1;  kc = (c - nc0) << 6; }
        const uint32_t sb = smb + (uint32_t)(c % 3) * STAGEB;
        #pragma unroll
        for (int it = 0; it < 4; it++) {            // A: 128 rows x 8 segs
            int idx = tid + it * 256;
            int row = idx >> 3, seg = idx & 7;
            uint32_t off = (uint32_t)(row * SSTR + seg * 8) * 2;
            CPA16(sb + off, A + (size_t)(m0 + row) * lda + kc + seg * 8);
        }
        #pragma unroll
        for (int it = 0; it < WIT; it++) {          // W: BN rows x 8 segs
            int idx = tid + it * 256;
            int row = idx >> 3, seg = idx & 7;
            uint32_t off = (uint32_t)(row * SSTR + seg * 8) * 2;
            CPA16(sb + A_BYTES + off, W + (size_t)(n0 + row) * ldw + kc + seg * 8);
        }
    };

    issue(0); CPCOMMIT();
    if (NC > 1) { issue(1); CPCOMMIT(); }

    for (int c = 0; c < NC; c++) {
        if (c + 1 < NC) CPWAIT1(); else CPWAIT0();  // stage c landed
        __syncthreads();                            // also: all warps done with c-1
        if (c + 2 < NC) { issue(c + 2); CPCOMMIT(); }  // overwrites stage of c-1: safe

        const uint32_t sb = smb + (uint32_t)(c % 3) * STAGEB;
        const uint32_t bA = sb;
        const uint32_t bW = sb + A_BYTES;

        #pragma unroll
        for (int kk = 0; kk < 64; kk += 16) {
            const int col = kk + ((lane >> 4) << 3);
            uint32_t a0[4], a1[4];
            {
                int row = wm * 32 + (lane & 15);
                ldm4(a0, bA + (uint32_t)(row * SSTR + col) * 2u);
                ldm4(a1, bA + (uint32_t)((row + 16) * SSTR + col) * 2u);
            }
            #pragma unroll
            for (int t = 0; t < N16T; t++) {
                uint32_t bh[4];
                int row = wn * WN + t * 16 + (lane & 15);
                ldm4(bh, bW + (uint32_t)(row * SSTR + col) * 2u);
                #pragma unroll
                for (int hs = 0; hs < 2; hs++) {
                    int nt = 2 * t + hs;
                    mma16816(acc[0][nt], a0, bh[hs], bh[2 + hs]);
                    mma16816(acc[1][nt], a1, bh[hs], bh[2 + hs]);
                }
            }
        }
    }

    if (EPI == 5) {
        // dual-job epilogue: gates (EPI1) or qout (bias+relu). No masking needed.
        #pragma unroll
        for (int mt = 0; mt < 2; mt++) {
            int r0 = m0 + wm * 32 + mt * 16 + (lane >> 2);
            int r1 = r0 + 8;
            int ib0 = 0, ib1 = 0;
            if (!isq) { ib0 = idxp[r0]; ib1 = idxp[r1]; }
            #pragma unroll
            for (int nt = 0; nt < NT8; nt++) {
                int cc = n0 + wn * WN + nt * 8 + ((lane & 3) << 1);
                #pragma unroll
                for (int p = 0; p < 2; p++) {
                    int r  = p ? r1 : r0;
                    float x = acc[mt][nt][2 * p];
                    float y = acc[mt][nt][2 * p + 1];
                    if (isq) {
                        x = fmaxf(x + biasq[cc], 0.f);
                        y = fmaxf(y + biasq[cc + 1], 0.f);
                        *reinterpret_cast<float2*>(&Cq[(size_t)r * ldcq + cc]) = make_float2(x, y);
                    } else {
                        int ib = p ? ib1 : ib0;
                        x += aux0[(size_t)ib * 1024 + cc];
                        y += aux0[(size_t)ib * 1024 + cc + 1];
                        *reinterpret_cast<float2*>(&C[(size_t)r * ldc + cc]) = make_float2(x, y);
                    }
                }
            }
        }
        return;
    }

    // ---- standard epilogue ----
    #pragma unroll
    for (int mt = 0; mt < 2; mt++) {
        int r0 = m0 + wm * 32 + mt * 16 + (lane >> 2);
        int r1 = r0 + 8;
        int ib0 = 0, ib1 = 0;
        if (EPI == 1) { ib0 = idxp[r0]; ib1 = idxp[r1]; }
        #pragma unroll
        for (int nt = 0; nt < NT8; nt++) {
            int cc = n0 + wn * WN + nt * 8 + ((lane & 3) << 1);
            if (cc < N) {
                float bb0 = 0.f, bb1 = 0.f;
                if (EPI != 1 && bias) {
                    if (cc < nsplit) { bb0 = bias[cc]; bb1 = bias[cc + 1]; }
                    else             { bb0 = bias2[cc - nsplit]; bb1 = bias2[cc + 1 - nsplit]; }
                }
                #pragma unroll
                for (int p = 0; p < 2; p++) {
                    int r  = p ? r1 : r0;
                    int ib = p ? ib1 : ib0;
                    float x = acc[mt][nt][2 * p];
                    float y = acc[mt][nt][2 * p + 1];
                    if (EPI == 1) {
                        x += aux0[(size_t)ib * 1024 + cc];
                        y += aux0[(size_t)ib * 1024 + cc + 1];
                    } else {
                        x += bb0; y += bb1;
                    }
                    if (ACT) { x = fmaxf(x, 0.f); y = fmaxf(y, 0.f); }
                    if (EPI == 2) {
                        x = tanhf(aux0[(size_t)r * 256 + cc] + x)     * aux1[(size_t)r * 512 + 256 + cc];
                        y = tanhf(aux0[(size_t)r * 256 + cc + 1] + y) * aux1[(size_t)r * 512 + 256 + cc + 1];
                    }
                    size_t o = (size_t)r * ldc + cc;
                    if (OUTM & 1)
                        *reinterpret_cast<float2*>(&C[o]) = make_float2(x, y);
                    if ((OUTM & 4) && cc >= 256)
                        *reinterpret_cast<float2*>(&C[o]) = make_float2(x, y);
                    if (OUTM & 2)
                        *reinterpret_cast<uint32_t*>(Ch + o) = pack2h(__float2half(x), __float2half(y));
                }
            }
        }
    }
}

// ---------------------------------------------------------------------------
// Final heads: pv2 [B,96] = pol2(0:64) | val2(64:96)
// ---------------------------------------------------------------------------
__global__ void k_heads(const float* __restrict__ pv2,
                        const float* __restrict__ w_p, const float* __restrict__ b_p,
                        const float* __restrict__ w_v, const float* __restrict__ b_v,
                        float* __restrict__ out_val, float* __restrict__ out_pol) {
    __shared__ float sp[64][97];
    int r0 = blockIdx.x * 64;
    for (int i = threadIdx.x; i < 64 * 96; i += blockDim.x) {
        int r = i / 96, c = i - r * 96;
        sp[r][c] = pv2[(size_t)(r0 + r) * 96 + c];
    }
    __syncthreads();
    int t = threadIdx.x;
    if (t < 64) {
        int b = r0 + t;
        float p0 = b_p[0], p1 = b_p[1], p2 = b_p[2];
        #pragma unroll
        for (int k = 0; k < 64; k++) {
            float x = sp[t][k];
            p0 = fmaf(x, w_p[k], p0);
            p1 = fmaf(x, w_p[64 + k], p1);
            p2 = fmaf(x, w_p[128 + k], p2);
        }
        out_pol[(size_t)b * 3 + 0] = p0;
        out_pol[(size_t)b * 3 + 1] = p1;
        out_pol[(size_t)b * 3 + 2] = p2;
        float v = b_v[0];
        #pragma unroll
        for (int k = 0; k < 32; k++) v = fmaf(sp[t][64 + k], w_v[k], v);
        out_val[b] = v;
    }
}

// ---------------------------------------------------------------------------
// host launcher
// ---------------------------------------------------------------------------
extern "C" void kernel_launch(void* const* d_in, const int* in_sizes, int n_in,
                              void* d_out, int out_size) {
    const float* img   = (const float*)d_in[0];
    const int*   idx   = (const int*)  d_in[1];
    const float* hx_in = (const float*)d_in[2];
    const float* cx_in = (const float*)d_in[3];
    const float* query = (const float*)d_in[4];
    const float* emb   = (const float*)d_in[5];
    const float* w_ta  = (const float*)d_in[6];
    const float* b_ta  = (const float*)d_in[7];
    const float* w_ih  = (const float*)d_in[8];
    const float* w_hh  = (const float*)d_in[9];
    const float* b_ih  = (const float*)d_in[10];
    const float* b_hh  = (const float*)d_in[11];
    const float* w_q   = (const float*)d_in[12];
    const float* b_q   = (const float*)d_in[13];
    const float* w_k   = (const float*)d_in[14];
    const float* b_k   = (const float*)d_in[15];
    const float* w_ba  = (const float*)d_in[16];
    const float* b_ba  = (const float*)d_in[17];
    const float* w_at  = (const float*)d_in[18];
    const float* b_at  = (const float*)d_in[19];
    const float* w_p1  = (const float*)d_in[20];
    const float* b_p1  = (const float*)d_in[21];
    const float* w_p2  = (const float*)d_in[22];
    const float* b_p2  = (const float*)d_in[23];
    const float* w_p   = (const float*)d_in[24];
    const float* b_p   = (const float*)d_in[25];
    const float* w_v1  = (const float*)d_in[26];
    const float* b_v1  = (const float*)d_in[27];
    const float* w_v2  = (const float*)d_in[28];
    const float* b_v2  = (const float*)d_in[29];
    const float* w_v   = (const float*)d_in[30];
    const float* b_v   = (const float*)d_in[31];

    const int B = in_sizes[0] / 256;  // 32768

    float* F = nullptr;
    cudaGetSymbolAddress((void**)&F, g_f32);
    __half* HF = nullptr;
    cudaGetSymbolAddress((void**)&HF, g_hf);

    float* tab   = F + F_TAB;
    float* pre2  = F + F_PRE2;
    float* gates = F + F_GATES;
    float* mlpf  = F + F_MLP;
    float* qout  = F + F_QOUT;
    float* pv2   = F + F_PV2;

    float* out   = (float*)d_out;
    float* o_val = out;
    float* o_pol = out + (size_t)B;
    float* o_hx  = out + (size_t)B * 4;
    float* o_cx  = o_hx + (size_t)B * 256;

    // smem: 3 stages; stage = 18432 + BN*144
    const int SM128 = 3 * (18432 + 128 * 144);  // 110592
    const int SM64  = 3 * (18432 + 64 * 144);   // 82944
    cudaFuncSetAttribute(mma_gemm<128, 0, 5, 1>, cudaFuncAttributeMaxDynamicSharedMemorySize, SM128);
    cudaFuncSetAttribute(mma_gemm<128, 1, 0, 6>, cudaFuncAttributeMaxDynamicSharedMemorySize, SM128);
    cudaFuncSetAttribute(mma_gemm<128, 1, 2, 2>, cudaFuncAttributeMaxDynamicSharedMemorySize, SM128);
    cudaFuncSetAttribute(mma_gemm<128, 1, 0, 2>, cudaFuncAttributeMaxDynamicSharedMemorySize, SM128);
    cudaFuncSetAttribute(mma_gemm<64, 1, 0, 2>,  cudaFuncAttributeMaxDynamicSharedMemorySize, SM64);
    cudaFuncSetAttribute(mma_gemm<64, 1, 0, 1>,  cudaFuncAttributeMaxDynamicSharedMemorySize, SM64);

    // K0: tables
    k0_tables<<<1, 1024>>>(emb, w_ta, b_ta, w_ih, b_ih, b_hh, tab, pre2);

    // fused weight convert (9 segments, one launch)
    {
        WAll d;
        auto seg = [&](int i, const float* src, int srcld, int cols, int rows, int padrows,
                       size_t hoff) {
            d.s[i] = WSeg{src, nullptr, srcld, cols, rows, padrows * cols, 0, (long long)hoff};
        };
        seg(0, w_ih, 512, 256, 1024, 1024, H_WIH);
        seg(1, w_hh, 256, 256, 1024, 1024, H_WHH);
        seg(2, w_ba, 512, 512, 512, 512, H_WBA);
        seg(3, w_q,  256, 256, 256, 256, H_WQ);
        seg(4, w_k,  256, 256, 256, 256, H_WK);
        seg(5, w_at, 512, 512, 256, 256, H_WAT);
        seg(6, w_p1, 256, 256, 128, 128, H_WPV);
        seg(7, w_v1, 256, 256, 64, 64, H_WPV + 128 * 256);
        d.s[8] = WSeg{w_p2, w_v2, 0, 0, 0, 128 * 192, 2, (long long)H_WC};
        int total = 0;
        for (int i = 0; i < 9; i++) total += d.s[i].total;
        k_wsplit_all<<<(total + 255) / 256, 256>>>(d, HF);
    }

    // fused prep
    k_prep<<<(3 * B * 64 + 255) / 256, 256>>>(
        (const float4*)img, idx, tab, (const float4*)hx_in, (const float4*)query,
        HF + H_FUS, HF + H_HXI, HF + H_QRY, B * 64);

    // K2+K5 merged: gates GEMM (x<8) + qout GEMM (x>=8)
    mma_gemm<128, 0, 5, 1><<<dim3(10, B / 128), 256, SM128>>>(
        1024,
        HF + H_FUS, 256, HF + H_WIH, 256, 256,
        HF + H_HXI, 256, HF + H_WHH, 256, 256,
        nullptr, nullptr, 1 << 30, pre2, nullptr, idx, gates, nullptr, 1024,
        HF + H_QRY, 256, HF + H_WQ, 256, 256, b_q, qout, 256, 8);

    // K3: LSTM
    k_lstm<<<(B * 64 + 255) / 256, 256>>>(gates, cx_in, o_hx, o_cx, HF + H_HXO, B * 64);

    // K4: mlp = relu([fus|hx] @ w_ba^T + b_ba)  (fp16 full + fp32 cols>=256 only)
    mma_gemm<128, 1, 0, 6><<<dim3(4, B / 128), 256, SM128>>>(
        512,
        HF + H_FUS, 256, HF + H_WBA, 512, 256,
        HF + H_HXO, 256, HF + H_WBA + 256, 512, 256,
        b_ba, nullptr, 1 << 30, nullptr, nullptr, nullptr, mlpf, HF + H_MLP, 512,
        nullptr, 0, nullptr, 0, 0, nullptr, nullptr, 0, 0);

    // K6: avec = tanh(qout + relu(key @ w_k^T + b_k)) * val  (fp16)
    mma_gemm<128, 1, 2, 2><<<dim3(2, B / 128), 256, SM128>>>(
        256,
        HF + H_MLP, 512, HF + H_WK, 256, 256,
        nullptr, 0, nullptr, 0, 0,
        b_k, nullptr, 1 << 30, qout, mlpf, nullptr, nullptr, HF + H_AVEC, 256,
        nullptr, 0, nullptr, 0, 0, nullptr, nullptr, 0, 0);

    // K7: attnw = relu([avec|hx] @ w_at^T + b_at)  (fp16)
    mma_gemm<128, 1, 0, 2><<<dim3(2, B / 128), 256, SM128>>>(
        256,
        HF + H_AVEC, 256, HF + H_WAT, 512, 256,
        HF + H_HXO, 256, HF + H_WAT + 256, 512, 256,
        b_at, nullptr, 1 << 30, nullptr, nullptr, nullptr, nullptr, HF + H_ATT, 256,
        nullptr, 0, nullptr, 0, 0, nullptr, nullptr, 0, 0);

    // K8: [pol1|val1] = relu(attnw @ [w_p1;w_v1]^T + [b_p1;b_v1])  N=192 (fp16)
    mma_gemm<64, 1, 0, 2><<<dim3(3, B / 128), 256, SM64>>>(
        192,
        HF + H_ATT, 256, HF + H_WPV, 256, 256,
        nullptr, 0, nullptr, 0, 0,
        b_p1, b_v1, 128, nullptr, nullptr, nullptr, nullptr, HF + H_P1V1, 192,
        nullptr, 0, nullptr, 0, 0, nullptr, nullptr, 0, 0);

    // K9: [pol2|val2] = relu([pol1|val1] @ blockdiag(w_p2,w_v2)^T + [b_p2;b_v2])  N=96 (fp32)
    mma_gemm<64, 1, 0, 1><<<dim3(2, B / 128), 256, SM64>>>(
        96,
        HF + H_P1V1, 192, HF + H_WC, 192, 192,
        nullptr, 0, nullptr, 0, 0,
        b_p2, b_v2, 64, nullptr, nullptr, nullptr, pv2, nullptr, 96,
        nullptr, 0, nullptr, 0, 0, nullptr, nullptr, 0, 0);

    // K10: heads
    k_heads<<<B / 64, 256>>>(pv2, w_p, b_p, w_v, b_v, o_val, o_pol);
}

// round 14
// speedup vs baseline: 1.1281x; 1.0275x over previous
#include <cuda_runtime.h>
#include <cuda_fp16.h>
#include <cstdint>
#include <math.h>

// ---------------------------------------------------------------------------
// Actor_Critic — single-pass fp16 MMA pipeline.
// 256-thread GEMM CTAs, K64 chunks, 3-stage cp.async ring, one barrier/chunk,
// 2 CTAs/SM. qout merged into gates launch (fp16 out); mlp fp32 buffer gone
// (K6 reads fp16); K9 GEMM fused with final heads.
// ---------------------------------------------------------------------------

constexpr size_t S_B = 32768;

// fp32 scratch
constexpr size_t F_TAB   = 0;
constexpr size_t F_PRE2  = 1024;
constexpr size_t F_GATES = 8192;
constexpr size_t F_END   = F_GATES + S_B * 1024;
__device__ float g_f32[F_END];

// fp16 scratch
constexpr size_t H_WIH   = 0;                        // 1024x256
constexpr size_t H_WHH   = H_WIH   + 262144;         // 1024x256
constexpr size_t H_WBA   = H_WHH   + 262144;         // 512x512
constexpr size_t H_WQ    = H_WBA   + 262144;         // 256x256
constexpr size_t H_WK    = H_WQ    + 65536;          // 256x256
constexpr size_t H_WAT   = H_WK    + 65536;          // 256x512
constexpr size_t H_WPV   = H_WAT   + 131072;         // 192x256
constexpr size_t H_WC    = H_WPV   + 49152;          // 128x192 block-diag
constexpr size_t H_FUS   = H_WC    + 24576;          // B*256
constexpr size_t H_HXI   = H_FUS   + S_B * 256;
constexpr size_t H_QRY   = H_HXI   + S_B * 256;
constexpr size_t H_HXO   = H_QRY   + S_B * 256;
constexpr size_t H_MLP   = H_HXO   + S_B * 256;      // B*512
constexpr size_t H_AVEC  = H_MLP   + S_B * 512;
constexpr size_t H_ATT   = H_AVEC  + S_B * 256;
constexpr size_t H_P1V1  = H_ATT   + S_B * 256;      // B*192
constexpr size_t H_QOUT  = H_P1V1  + S_B * 192;      // B*256 (fp16 qout)
constexpr size_t H_END   = H_QOUT  + S_B * 256;
__device__ __half g_hf[H_END];

__device__ __forceinline__ float sigmoidf_(float x) { return 1.f / (1.f + expf(-x)); }
__device__ __forceinline__ uint32_t pack2h(__half a, __half b) {
    return (uint32_t)__half_as_ushort(a) | ((uint32_t)__half_as_ushort(b) << 16);
}

// ---------------------------------------------------------------------------
// K0: gated_att table (4x256) + pre2 table (4x1024)
// ---------------------------------------------------------------------------
__global__ void k0_tables(const float* __restrict__ emb,  const float* __restrict__ w_ta,
                          const float* __restrict__ b_ta, const float* __restrict__ w_ih,
                          const float* __restrict__ b_ih, const float* __restrict__ b_hh,
                          float* __restrict__ tab, float* __restrict__ pre2) {
    int t = threadIdx.x;  // 1024
    {
        int r = t >> 8, j = t & 255;
        float s = b_ta[j];
        #pragma unroll
        for (int k = 0; k < 25; k++) s += emb[r * 25 + k] * w_ta[j * 25 + k];
        tab[t] = sigmoidf_(s);
    }
    __syncthreads();
    {
        int j = t;
        const float* wrow = &w_ih[(size_t)j * 512 + 256];
        float base = b_ih[j] + b_hh[j];
        for (int r = 0; r < 4; r++) {
            const float* tr = &tab[r * 256];
            float s = base;
            for (int k = 0; k < 256; k++) s += tr[k] * wrow[k];
            pre2[r * 1024 + j] = s;
        }
    }
}

// ---------------------------------------------------------------------------
// fused weight convert to fp16. mode 0: normal; mode 2: p2/v2 block-diag.
// ---------------------------------------------------------------------------
struct WSeg { const float* src; const float* src2; int srcld, cols, rows, total, mode;
              long long hoff; };
struct WAll { WSeg s[9]; };

__global__ void k_wsplit_all(WAll d, __half* __restrict__ base) {
    int i = blockIdx.x * blockDim.x + threadIdx.x;
    #pragma unroll
    for (int s = 0; s < 9; s++) {
        const WSeg& g = d.s[s];
        if (i < g.total) {
            float v;
            if (g.mode == 0) {
                int r = i / g.cols, c = i - r * g.cols;
                v = (r < g.rows) ? g.src[(size_t)r * g.srcld + c] : 0.f;
            } else {
                int r = i / 192, c = i - r * 192;
                if (r < 64)       v = (c < 128) ? g.src[r * 128 + c] : 0.f;
                else if (c >= 128 && r - 64 < 32) v = g.src2[(r - 64) * 64 + (c - 128)];
                else              v = 0.f;
            }
            base[g.hoff + i] = __float2half(v);
            return;
        }
        i -= g.total;
    }
}

// ---------------------------------------------------------------------------
// fused prep: region 0 fusion(img*tab[idx]); 1: round hx_in; 2: round query
// ---------------------------------------------------------------------------
__global__ void k_prep(const float4* __restrict__ img, const int* __restrict__ idx,
                       const float* __restrict__ tab,
                       const float4* __restrict__ hx_in, const float4* __restrict__ query,
                       __half* __restrict__ fus, __half* __restrict__ hxi,
                       __half* __restrict__ qry, int nq) {
    int i = blockIdx.x * blockDim.x + threadIdx.x;
    int reg = 0;
    if (i >= nq) { i -= nq; reg = 1; }
    if (i >= nq) { i -= nq; reg = 2; }
    if (i >= nq) return;
    float4 v;
    __half* dst;
    if (reg == 0) {
        int b = i >> 6, j4 = (i & 63) << 2;
        float4 g = *reinterpret_cast<const float4*>(tab + idx[b] * 256 + j4);
        v = img[i];
        v.x *= g.x; v.y *= g.y; v.z *= g.z; v.w *= g.w;
        dst = fus;
    } else if (reg == 1) { v = hx_in[i]; dst = hxi; }
    else                 { v = query[i]; dst = qry; }
    uint2 u = make_uint2(pack2h(__float2half(v.x), __float2half(v.y)),
                         pack2h(__float2half(v.z), __float2half(v.w)));
    *reinterpret_cast<uint2*>(dst + (size_t)i * 4) = u;
}

// ---------------------------------------------------------------------------
// K3: LSTM -> hx,cx fp32 (outputs) + hx fp16
// ---------------------------------------------------------------------------
__global__ void k_lstm(const float* __restrict__ gates, const float* __restrict__ cx_in,
                       float* __restrict__ hx_out, float* __restrict__ cx_out,
                       __half* __restrict__ hxo, int totalq) {
    int i = blockIdx.x * blockDim.x + threadIdx.x;
    if (i >= totalq) return;
    int b = i >> 6, j = (i & 63) << 2;
    const float* g = gates + (size_t)b * 1024 + j;
    float4 gi = *reinterpret_cast<const float4*>(g);
    float4 gf = *reinterpret_cast<const float4*>(g + 256);
    float4 gg = *reinterpret_cast<const float4*>(g + 512);
    float4 go = *reinterpret_cast<const float4*>(g + 768);
    float4 c0 = *reinterpret_cast<const float4*>(cx_in + (size_t)b * 256 + j);
    float4 ho, co;
    co.x = sigmoidf_(gf.x) * c0.x + sigmoidf_(gi.x) * tanhf(gg.x); ho.x = sigmoidf_(go.x) * tanhf(co.x);
    co.y = sigmoidf_(gf.y) * c0.y + sigmoidf_(gi.y) * tanhf(gg.y); ho.y = sigmoidf_(go.y) * tanhf(co.y);
    co.z = sigmoidf_(gf.z) * c0.z + sigmoidf_(gi.z) * tanhf(gg.z); ho.z = sigmoidf_(go.z) * tanhf(co.z);
    co.w = sigmoidf_(gf.w) * c0.w + sigmoidf_(gi.w) * tanhf(gg.w); ho.w = sigmoidf_(go.w) * tanhf(co.w);
    size_t o = (size_t)b * 256 + j;
    *reinterpret_cast<float4*>(hx_out + o) = ho;
    *reinterpret_cast<float4*>(cx_out + o) = co;
    uint2 u = make_uint2(pack2h(__float2half(ho.x), __float2half(ho.y)),
                         pack2h(__float2half(ho.z), __float2half(ho.w)));
    *reinterpret_cast<uint2*>(hxo + o) = u;
}

// ---------------------------------------------------------------------------
// MMA / cp.async helpers
// ---------------------------------------------------------------------------
__device__ __forceinline__ void ldm4(uint32_t* r, uint32_t addr) {
    asm volatile("ldmatrix.sync.aligned.m8n8.x4.shared.b16 {%0,%1,%2,%3}, [%4];"
                 : "=r"(r[0]), "=r"(r[1]), "=r"(r[2]), "=r"(r[3]) : "r"(addr));
}
__device__ __forceinline__ void mma16816(float* c, const uint32_t* a, uint32_t b0, uint32_t b1) {
    asm volatile(
        "mma.sync.aligned.m16n8k16.row.col.f32.f16.f16.f32 "
        "{%0,%1,%2,%3}, {%4,%5,%6,%7}, {%8,%9}, {%0,%1,%2,%3};"
        : "+f"(c[0]), "+f"(c[1]), "+f"(c[2]), "+f"(c[3])
        : "r"(a[0]), "r"(a[1]), "r"(a[2]), "r"(a[3]), "r"(b0), "r"(b1));
}
#define CPA16(dst, src) asm volatile("cp.async.cg.shared.global [%0], [%1], 16;\n" :: "r"(dst), "l"(src))
#define CPCOMMIT()      asm volatile("cp.async.commit_group;\n")
#define CPWAIT1()       asm volatile("cp.async.wait_group 1;\n")
#define CPWAIT0()       asm volatile("cp.async.wait_group 0;\n")

// ---------------------------------------------------------------------------
// GEMM: C = epi( sum_seg A_seg @ W_seg^T ), fp16 single pass, fp32 acc.
// 256 threads, 8 warps (4m x 2n), BM=128, K64 chunks (144B rows), 3-stage
// cp.async ring, one barrier/chunk. 2 CTAs/SM.
// EPI 0: +bias (split at nsplit), relu if ACT
// EPI 2: (+bias, relu) -> tanh(qout_h + v) * mlp_h[.,256+n]   (fp16 aux)
// EPI 4: (+bias split, relu) -> stage smem -> fused heads (pol/val) direct out
// EPI 5: dual-job: blockIdx.x < gx1 -> gates (+pre2 via idxp, fp32 C);
//        else qout job (Aq,Wq,Kq, +biasq, relu, fp16 Cqh)
// OUTM bit0: fp32 C; bit1: fp16 Ch.
// ---------------------------------------------------------------------------
template <int BN, int ACT, int EPI, int OUTM>
__global__ void __launch_bounds__(256, 2)
mma_gemm(int N,
         const __half* __restrict__ A0, int lda0,
         const __half* __restrict__ W0, int ldw0, int K0,
         const __half* __restrict__ A1, int lda1,
         const __half* __restrict__ W1, int ldw1, int K1,
         const float* __restrict__ bias, const float* __restrict__ bias2, int nsplit,
         const __half* __restrict__ auxh0, const __half* __restrict__ auxh1,
         const float* __restrict__ aux0,
         const int* __restrict__ idxp,
         float* __restrict__ C, __half* __restrict__ Ch, int ldc,
         const __half* __restrict__ Aq, int ldaq,
         const __half* __restrict__ Wq, int ldwq, int Kq,
         const float* __restrict__ biasq, __half* __restrict__ Cqh, int ldcq, int gx1,
         const float* __restrict__ hw_p, const float* __restrict__ hb_p,
         const float* __restrict__ hw_v, const float* __restrict__ hb_v,
         float* __restrict__ o_val, float* __restrict__ o_pol) {
    constexpr int WN      = BN / 2;                 // warp n-extent (2 warps in n)
    constexpr int NT8     = WN / 8;
    constexpr int N16T    = WN / 16;
    constexpr int SSTR    = 72;                     // halves/row: 64 data + 8 pad (144B)
    constexpr int A_BYTES = 128 * SSTR * 2;         // 18432
    constexpr int W_BYTES = BN * SSTR * 2;
    constexpr int STAGEB  = A_BYTES + W_BYTES;
    constexpr int WIT     = BN / 32;                // W cp.async iters

    extern __shared__ __half smem_dyn[];

    const int tid  = threadIdx.x;
    const int lane = tid & 31;
    const int wid  = tid >> 5;
    const int wm = wid & 3, wn = wid >> 2;          // 4 x 2 warps
    const int m0 = blockIdx.y * 128;

    const bool isq = (EPI == 5) && ((int)blockIdx.x >= gx1);
    const int n0 = (isq ? ((int)blockIdx.x - gx1) : (int)blockIdx.x) * BN;

    const __half* jA0 = isq ? Aq : A0;  const int jlda0 = isq ? ldaq : lda0;
    const __half* jW0 = isq ? Wq : W0;  const int jldw0 = isq ? ldwq : ldw0;
    const int jK0 = isq ? Kq : K0;
    const int jK1 = isq ? 0  : K1;

    const uint32_t smb = (uint32_t)__cvta_generic_to_shared(smem_dyn);

    float acc[2][NT8][4];
    #pragma unroll
    for (int i = 0; i < 2; i++)
        #pragma unroll
        for (int j = 0; j < NT8; j++)
            #pragma unroll
            for (int q = 0; q < 4; q++) acc[i][j][q] = 0.f;

    const int nc0 = jK0 >> 6;
    const int NC  = nc0 + (jK1 >> 6);

    auto issue = [&](int c) {
        const __half *A, *W;
        int lda, ldw, kc;
        if (c < nc0) { A = jA0; W = jW0; lda = jlda0; ldw = jldw0; kc = c << 6; }
        else         { A = A1;  W = W1;  lda = lda1;  ldw = ldw1;  kc = (c - nc0) << 6; }
        const uint32_t sb = smb + (uint32_t)(c % 3) * STAGEB;
        #pragma unroll
        for (int it = 0; it < 4; it++) {            // A: 128 rows x 8 segs
            int idx = tid + it * 256;
            int row = idx >> 3, seg = idx & 7;
            uint32_t off = (uint32_t)(row * SSTR + seg * 8) * 2;
            CPA16(sb + off, A + (size_t)(m0 + row) * lda + kc + seg * 8);
        }
        #pragma unroll
        for (int it = 0; it < WIT; it++) {          // W: BN rows x 8 segs
            int idx = tid + it * 256;
            int row = idx >> 3, seg = idx & 7;
            uint32_t off = (uint32_t)(row * SSTR + seg * 8) * 2;
            CPA16(sb + A_BYTES + off, W + (size_t)(n0 + row) * ldw + kc + seg * 8);
        }
    };

    issue(0); CPCOMMIT();
    if (NC > 1) { issue(1); CPCOMMIT(); }

    for (int c = 0; c < NC; c++) {
        if (c + 1 < NC) CPWAIT1(); else CPWAIT0();
        __syncthreads();
        if (c + 2 < NC) { issue(c + 2); CPCOMMIT(); }

        const uint32_t sb = smb + (uint32_t)(c % 3) * STAGEB;
        const uint32_t bA = sb;
        const uint32_t bW = sb + A_BYTES;

        #pragma unroll
        for (int kk = 0; kk < 64; kk += 16) {
            const int col = kk + ((lane >> 4) << 3);
            uint32_t a0[4], a1[4];
            {
                int row = wm * 32 + (lane & 15);
                ldm4(a0, bA + (uint32_t)(row * SSTR + col) * 2u);
                ldm4(a1, bA + (uint32_t)((row + 16) * SSTR + col) * 2u);
            }
            #pragma unroll
            for (int t = 0; t < N16T; t++) {
                uint32_t bh[4];
                int row = wn * WN + t * 16 + (lane & 15);
                ldm4(bh, bW + (uint32_t)(row * SSTR + col) * 2u);
                #pragma unroll
                for (int hs = 0; hs < 2; hs++) {
                    int nt = 2 * t + hs;
                    mma16816(acc[0][nt], a0, bh[hs], bh[2 + hs]);
                    mma16816(acc[1][nt], a1, bh[hs], bh[2 + hs]);
                }
            }
        }
    }

    if (EPI == 5) {
        #pragma unroll
        for (int mt = 0; mt < 2; mt++) {
            int r0 = m0 + wm * 32 + mt * 16 + (lane >> 2);
            int r1 = r0 + 8;
            int ib0 = 0, ib1 = 0;
            if (!isq) { ib0 = idxp[r0]; ib1 = idxp[r1]; }
            #pragma unroll
            for (int nt = 0; nt < NT8; nt++) {
                int cc = n0 + wn * WN + nt * 8 + ((lane & 3) << 1);
                #pragma unroll
                for (int p = 0; p < 2; p++) {
                    int r  = p ? r1 : r0;
                    float x = acc[mt][nt][2 * p];
                    float y = acc[mt][nt][2 * p + 1];
                    if (isq) {
                        x = fmaxf(x + biasq[cc], 0.f);
                        y = fmaxf(y + biasq[cc + 1], 0.f);
                        *reinterpret_cast<uint32_t*>(&Cqh[(size_t)r * ldcq + cc]) =
                            pack2h(__float2half(x), __float2half(y));
                    } else {
                        int ib = p ? ib1 : ib0;
                        x += aux0[(size_t)ib * 1024 + cc];
                        y += aux0[(size_t)ib * 1024 + cc + 1];
                        *reinterpret_cast<float2*>(&C[(size_t)r * ldc + cc]) = make_float2(x, y);
                    }
                }
            }
        }
        return;
    }

    if (EPI == 4) {
        // ---- fused pol2/val2 + heads epilogue (n0 == 0, N == 96) ----
        __syncthreads();                            // pipeline smem reusable
        float* sf = reinterpret_cast<float*>(smem_dyn);   // stride 98 floats
        #pragma unroll
        for (int mt = 0; mt < 2; mt++) {
            int rl0 = wm * 32 + mt * 16 + (lane >> 2);
            #pragma unroll
            for (int nt = 0; nt < NT8; nt++) {
                int cc = wn * WN + nt * 8 + ((lane & 3) << 1);
                float bb0 = (cc < nsplit) ? bias[cc] : bias2[cc - nsplit];
                float bb1 = (cc < nsplit) ? bias[cc + 1] : bias2[cc + 1 - nsplit];
                #pragma unroll
                for (int p = 0; p < 2; p++) {
                    int rl = rl0 + p * 8;
                    float x = fmaxf(acc[mt][nt][2 * p] + bb0, 0.f);
                    float y = fmaxf(acc[mt][nt][2 * p + 1] + bb1, 0.f);
                    *reinterpret_cast<float2*>(&sf[rl * 98 + cc]) = make_float2(x, y);
                }
            }
        }
        __syncthreads();
        if (tid < 128) {
            int b = m0 + tid;
            const float* row = &sf[tid * 98];
            float p0 = hb_p[0], p1 = hb_p[1], p2 = hb_p[2];
            #pragma unroll
            for (int k = 0; k < 64; k++) {
                float xv = row[k];
                p0 = fmaf(xv, hw_p[k], p0);
                p1 = fmaf(xv, hw_p[64 + k], p1);
                p2 = fmaf(xv, hw_p[128 + k], p2);
            }
            o_pol[(size_t)b * 3 + 0] = p0;
            o_pol[(size_t)b * 3 + 1] = p1;
            o_pol[(size_t)b * 3 + 2] = p2;
            float v = hb_v[0];
            #pragma unroll
            for (int k = 0; k < 32; k++) v = fmaf(row[64 + k], hw_v[k], v);
            o_val[b] = v;
        }
        return;
    }

    // ---- standard epilogue (EPI 0 / 2) ----
    #pragma unroll
    for (int mt = 0; mt < 2; mt++) {
        int r0 = m0 + wm * 32 + mt * 16 + (lane >> 2);
        int r1 = r0 + 8;
        #pragma unroll
        for (int nt = 0; nt < NT8; nt++) {
            int cc = n0 + wn * WN + nt * 8 + ((lane & 3) << 1);
            if (cc < N) {
                float bb0 = 0.f, bb1 = 0.f;
                if (bias) {
                    if (cc < nsplit) { bb0 = bias[cc]; bb1 = bias[cc + 1]; }
                    else             { bb0 = bias2[cc - nsplit]; bb1 = bias2[cc + 1 - nsplit]; }
                }
                #pragma unroll
                for (int p = 0; p < 2; p++) {
                    int r = p ? r1 : r0;
                    float x = acc[mt][nt][2 * p] + bb0;
                    float y = acc[mt][nt][2 * p + 1] + bb1;
                    if (ACT) { x = fmaxf(x, 0.f); y = fmaxf(y, 0.f); }
                    if (EPI == 2) {
                        __half2 q2 = *reinterpret_cast<const __half2*>(&auxh0[(size_t)r * 256 + cc]);
                        __half2 v2 = *reinterpret_cast<const __half2*>(&auxh1[(size_t)r * 512 + 256 + cc]);
                        x = tanhf(__low2float(q2) + x)  * __low2float(v2);
                        y = tanhf(__high2float(q2) + y) * __high2float(v2);
                    }
                    size_t o = (size_t)r * ldc + cc;
                    if (OUTM & 1)
                        *reinterpret_cast<float2*>(&C[o]) = make_float2(x, y);
                    if (OUTM & 2)
                        *reinterpret_cast<uint32_t*>(Ch + o) = pack2h(__float2half(x), __float2half(y));
                }
            }
        }
    }
}

// ---------------------------------------------------------------------------
// host launcher
// ---------------------------------------------------------------------------
extern "C" void kernel_launch(void* const* d_in, const int* in_sizes, int n_in,
                              void* d_out, int out_size) {
    const float* img   = (const float*)d_in[0];
    const int*   idx   = (const int*)  d_in[1];
    const float* hx_in = (const float*)d_in[2];
    const float* cx_in = (const float*)d_in[3];
    const float* query = (const float*)d_in[4];
    const float* emb   = (const float*)d_in[5];
    const float* w_ta  = (const float*)d_in[6];
    const float* b_ta  = (const float*)d_in[7];
    const float* w_ih  = (const float*)d_in[8];
    const float* w_hh  = (const float*)d_in[9];
    const float* b_ih  = (const float*)d_in[10];
    const float* b_hh  = (const float*)d_in[11];
    const float* w_q   = (const float*)d_in[12];
    const float* b_q   = (const float*)d_in[13];
    const float* w_k   = (const float*)d_in[14];
    const float* b_k   = (const float*)d_in[15];
    const float* w_ba  = (const float*)d_in[16];
    const float* b_ba  = (const float*)d_in[17];
    const float* w_at  = (const float*)d_in[18];
    const float* b_at  = (const float*)d_in[19];
    const float* w_p1  = (const float*)d_in[20];
    const float* b_p1  = (const float*)d_in[21];
    const float* w_p2  = (const float*)d_in[22];
    const float* b_p2  = (const float*)d_in[23];
    const float* w_p   = (const float*)d_in[24];
    const float* b_p   = (const float*)d_in[25];
    const float* w_v1  = (const float*)d_in[26];
    const float* b_v1  = (const float*)d_in[27];
    const float* w_v2  = (const float*)d_in[28];
    const float* b_v2  = (const float*)d_in[29];
    const float* w_v   = (const float*)d_in[30];
    const float* b_v   = (const float*)d_in[31];

    const int B = in_sizes[0] / 256;  // 32768

    float* F = nullptr;
    cudaGetSymbolAddress((void**)&F, g_f32);
    __half* HF = nullptr;
    cudaGetSymbolAddress((void**)&HF, g_hf);

    float* tab   = F + F_TAB;
    float* pre2  = F + F_PRE2;
    float* gates = F + F_GATES;

    float* out   = (float*)d_out;
    float* o_val = out;
    float* o_pol = out + (size_t)B;
    float* o_hx  = out + (size_t)B * 4;
    float* o_cx  = o_hx + (size_t)B * 256;

    // smem: 3 stages; stage = 18432 + BN*144
    const int SM128 = 3 * (18432 + 128 * 144);  // 110592
    const int SM96  = 3 * (18432 + 96 * 144);   // 96768 (EPI4 staging 50176 fits)
    const int SM64  = 3 * (18432 + 64 * 144);   // 82944
    cudaFuncSetAttribute(mma_gemm<128, 0, 5, 1>, cudaFuncAttributeMaxDynamicSharedMemorySize, SM128);
    cudaFuncSetAttribute(mma_gemm<128, 1, 0, 2>, cudaFuncAttributeMaxDynamicSharedMemorySize, SM128);
    cudaFuncSetAttribute(mma_gemm<128, 1, 2, 2>, cudaFuncAttributeMaxDynamicSharedMemorySize, SM128);
    cudaFuncSetAttribute(mma_gemm<64, 1, 0, 2>,  cudaFuncAttributeMaxDynamicSharedMemorySize, SM64);
    cudaFuncSetAttribute(mma_gemm<96, 1, 4, 0>,  cudaFuncAttributeMaxDynamicSharedMemorySize, SM96);

    // K0: tables
    k0_tables<<<1, 1024>>>(emb, w_ta, b_ta, w_ih, b_ih, b_hh, tab, pre2);

    // fused weight convert (9 segments, one launch)
    {
        WAll d;
        auto seg = [&](int i, const float* src, int srcld, int cols, int rows, int padrows,
                       size_t hoff) {
            d.s[i] = WSeg{src, nullptr, srcld, cols, rows, padrows * cols, 0, (long long)hoff};
        };
        seg(0, w_ih, 512, 256, 1024, 1024, H_WIH);
        seg(1, w_hh, 256, 256, 1024, 1024, H_WHH);
        seg(2, w_ba, 512, 512, 512, 512, H_WBA);
        seg(3, w_q,  256, 256, 256, 256, H_WQ);
        seg(4, w_k,  256, 256, 256, 256, H_WK);
        seg(5, w_at, 512, 512, 256, 256, H_WAT);
        seg(6, w_p1, 256, 256, 128, 128, H_WPV);
        seg(7, w_v1, 256, 256, 64, 64, H_WPV + 128 * 256);
        d.s[8] = WSeg{w_p2, w_v2, 0, 0, 0, 128 * 192, 2, (long long)H_WC};
        int total = 0;
        for (int i = 0; i < 9; i++) total += d.s[i].total;
        k_wsplit_all<<<(total + 255) / 256, 256>>>(d, HF);
    }

    // fused prep
    k_prep<<<(3 * B * 64 + 255) / 256, 256>>>(
        (const float4*)img, idx, tab, (const float4*)hx_in, (const float4*)query,
        HF + H_FUS, HF + H_HXI, HF + H_QRY, B * 64);

    // K2+K5 merged: gates GEMM (x<8, fp32 out) + qout GEMM (x>=8, fp16 out)
    mma_gemm<128, 0, 5, 1><<<dim3(10, B / 128), 256, SM128>>>(
        1024,
        HF + H_FUS, 256, HF + H_WIH, 256, 256,
        HF + H_HXI, 256, HF + H_WHH, 256, 256,
        nullptr, nullptr, 1 << 30, nullptr, nullptr, pre2, idx, gates, nullptr, 1024,
        HF + H_QRY, 256, HF + H_WQ, 256, 256, b_q, HF + H_QOUT, 256, 8,
        nullptr, nullptr, nullptr, nullptr, nullptr, nullptr);

    // K3: LSTM
    k_lstm<<<(B * 64 + 255) / 256, 256>>>(gates, cx_in, o_hx, o_cx, HF + H_HXO, B * 64);

    // K4: mlp = relu([fus|hx] @ w_ba^T + b_ba)  (fp16 only)
    mma_gemm<128, 1, 0, 2><<<dim3(4, B / 128), 256, SM128>>>(
        512,
        HF + H_FUS, 256, HF + H_WBA, 512, 256,
        HF + H_HXO, 256, HF + H_WBA + 256, 512, 256,
        b_ba, nullptr, 1 << 30, nullptr, nullptr, nullptr, nullptr, nullptr, HF + H_MLP, 512,
        nullptr, 0, nullptr, 0, 0, nullptr, nullptr, 0, 0,
        nullptr, nullptr, nullptr, nullptr, nullptr, nullptr);

    // K6: avec = tanh(qout_h + relu(key @ w_k^T + b_k)) * mlp_h[.,256+n]  (fp16)
    mma_gemm<128, 1, 2, 2><<<dim3(2, B / 128), 256, SM128>>>(
        256,
        HF + H_MLP, 512, HF + H_WK, 256, 256,
        nullptr, 0, nullptr, 0, 0,
        b_k, nullptr, 1 << 30, HF + H_QOUT, HF + H_MLP, nullptr, nullptr,
        nullptr, HF + H_AVEC, 256,
        nullptr, 0, nullptr, 0, 0, nullptr, nullptr, 0, 0,
        nullptr, nullptr, nullptr, nullptr, nullptr, nullptr);

    // K7: attnw = relu([avec|hx] @ w_at^T + b_at)  (fp16)
    mma_gemm<128, 1, 0, 2><<<dim3(2, B / 128), 256, SM128>>>(
        256,
        HF + H_AVEC, 256, HF + H_WAT, 512, 256,
        HF + H_HXO, 256, HF + H_WAT + 256, 512, 256,
        b_at, nullptr, 1 << 30, nullptr, nullptr, nullptr, nullptr, nullptr, HF + H_ATT, 256,
        nullptr, 0, nullptr, 0, 0, nullptr, nullptr, 0, 0,
        nullptr, nullptr, nullptr, nullptr, nullptr, nullptr);

    // K8: [pol1|val1] = relu(attnw @ [w_p1;w_v1]^T + [b_p1;b_v1])  N=192 (fp16)
    mma_gemm<64, 1, 0, 2><<<dim3(3, B / 128), 256, SM64>>>(
        192,
        HF + H_ATT, 256, HF + H_WPV, 256, 256,
        nullptr, 0, nullptr, 0, 0,
        b_p1, b_v1, 128, nullptr, nullptr, nullptr, nullptr, nullptr, HF + H_P1V1, 192,
        nullptr, 0, nullptr, 0, 0, nullptr, nullptr, 0, 0,
        nullptr, nullptr, nullptr, nullptr, nullptr, nullptr);

    // K9 fused with heads: [pol2|val2] GEMM (N=96, blockdiag) -> pol/val outputs
    mma_gemm<96, 1, 4, 0><<<dim3(1, B / 128), 256, SM96>>>(
        96,
        HF + H_P1V1, 192, HF + H_WC, 192, 192,
        nullptr, 0, nullptr, 0, 0,
        b_p2, b_v2, 64, nullptr, nullptr, nullptr, nullptr, nullptr, nullptr, 96,
        nullptr, 0, nullptr, 0, 0, nullptr, nullptr, 0, 0,
        w_p, b_p, w_v, b_v, o_val, o_pol);
}

// round 15
// speedup vs baseline: 1.1357x; 1.0068x over previous
#include <cuda_runtime.h>
#include <cuda_fp16.h>
#include <cstdint>
#include <math.h>

// ---------------------------------------------------------------------------
// Actor_Critic — single-pass fp16 MMA pipeline.
// 256-thread GEMM CTAs, K64 chunks, 3-stage cp.async ring, one barrier/chunk,
// 2 CTAs/SM. qout merged into gates launch (fp16); gates buffer fp16;
// K9 GEMM fused with final heads.
// ---------------------------------------------------------------------------

constexpr size_t S_B = 32768;

// fp32 scratch
constexpr size_t F_TAB   = 0;
constexpr size_t F_PRE2  = 1024;
constexpr size_t F_END   = F_PRE2 + 4096;
__device__ float g_f32[F_END];

// fp16 scratch
constexpr size_t H_WIH   = 0;                        // 1024x256
constexpr size_t H_WHH   = H_WIH   + 262144;         // 1024x256
constexpr size_t H_WBA   = H_WHH   + 262144;         // 512x512
constexpr size_t H_WQ    = H_WBA   + 262144;         // 256x256
constexpr size_t H_WK    = H_WQ    + 65536;          // 256x256
constexpr size_t H_WAT   = H_WK    + 65536;          // 256x512
constexpr size_t H_WPV   = H_WAT   + 131072;         // 192x256
constexpr size_t H_WC    = H_WPV   + 49152;          // 128x192 block-diag
constexpr size_t H_FUS   = H_WC    + 24576;          // B*256
constexpr size_t H_HXI   = H_FUS   + S_B * 256;
constexpr size_t H_QRY   = H_HXI   + S_B * 256;
constexpr size_t H_HXO   = H_QRY   + S_B * 256;
constexpr size_t H_MLP   = H_HXO   + S_B * 256;      // B*512
constexpr size_t H_AVEC  = H_MLP   + S_B * 512;
constexpr size_t H_ATT   = H_AVEC  + S_B * 256;
constexpr size_t H_P1V1  = H_ATT   + S_B * 256;      // B*192
constexpr size_t H_QOUT  = H_P1V1  + S_B * 192;      // B*256 (fp16 qout)
constexpr size_t H_GATES = H_QOUT  + S_B * 256;      // B*1024 (fp16 gates)
constexpr size_t H_END   = H_GATES + S_B * 1024;
__device__ __half g_hf[H_END];

__device__ __forceinline__ float sigmoidf_(float x) { return 1.f / (1.f + expf(-x)); }
__device__ __forceinline__ uint32_t pack2h(__half a, __half b) {
    return (uint32_t)__half_as_ushort(a) | ((uint32_t)__half_as_ushort(b) << 16);
}

// ---------------------------------------------------------------------------
// K0: gated_att table (4x256) + pre2 table (4x1024)
// ---------------------------------------------------------------------------
__global__ void k0_tables(const float* __restrict__ emb,  const float* __restrict__ w_ta,
                          const float* __restrict__ b_ta, const float* __restrict__ w_ih,
                          const float* __restrict__ b_ih, const float* __restrict__ b_hh,
                          float* __restrict__ tab, float* __restrict__ pre2) {
    int t = threadIdx.x;  // 1024
    {
        int r = t >> 8, j = t & 255;
        float s = b_ta[j];
        #pragma unroll
        for (int k = 0; k < 25; k++) s += emb[r * 25 + k] * w_ta[j * 25 + k];
        tab[t] = sigmoidf_(s);
    }
    __syncthreads();
    {
        int j = t;
        const float* wrow = &w_ih[(size_t)j * 512 + 256];
        float base = b_ih[j] + b_hh[j];
        for (int r = 0; r < 4; r++) {
            const float* tr = &tab[r * 256];
            float s = base;
            for (int k = 0; k < 256; k++) s += tr[k] * wrow[k];
            pre2[r * 1024 + j] = s;
        }
    }
}

// ---------------------------------------------------------------------------
// fused weight convert to fp16. mode 0: normal; mode 2: p2/v2 block-diag.
// ---------------------------------------------------------------------------
struct WSeg { const float* src; const float* src2; int srcld, cols, rows, total, mode;
              long long hoff; };
struct WAll { WSeg s[9]; };

__global__ void k_wsplit_all(WAll d, __half* __restrict__ base) {
    int i = blockIdx.x * blockDim.x + threadIdx.x;
    #pragma unroll
    for (int s = 0; s < 9; s++) {
        const WSeg& g = d.s[s];
        if (i < g.total) {
            float v;
            if (g.mode == 0) {
                int r = i / g.cols, c = i - r * g.cols;
                v = (r < g.rows) ? g.src[(size_t)r * g.srcld + c] : 0.f;
            } else {
                int r = i / 192, c = i - r * 192;
                if (r < 64)       v = (c < 128) ? g.src[r * 128 + c] : 0.f;
                else if (c >= 128 && r - 64 < 32) v = g.src2[(r - 64) * 64 + (c - 128)];
                else              v = 0.f;
            }
            base[g.hoff + i] = __float2half(v);
            return;
        }
        i -= g.total;
    }
}

// ---------------------------------------------------------------------------
// fused prep: region 0 fusion(img*tab[idx]); 1: round hx_in; 2: round query
// ---------------------------------------------------------------------------
__global__ void k_prep(const float4* __restrict__ img, const int* __restrict__ idx,
                       const float* __restrict__ tab,
                       const float4* __restrict__ hx_in, const float4* __restrict__ query,
                       __half* __restrict__ fus, __half* __restrict__ hxi,
                       __half* __restrict__ qry, int nq) {
    int i = blockIdx.x * blockDim.x + threadIdx.x;
    int reg = 0;
    if (i >= nq) { i -= nq; reg = 1; }
    if (i >= nq) { i -= nq; reg = 2; }
    if (i >= nq) return;
    float4 v;
    __half* dst;
    if (reg == 0) {
        int b = i >> 6, j4 = (i & 63) << 2;
        float4 g = *reinterpret_cast<const float4*>(tab + idx[b] * 256 + j4);
        v = img[i];
        v.x *= g.x; v.y *= g.y; v.z *= g.z; v.w *= g.w;
        dst = fus;
    } else if (reg == 1) { v = hx_in[i]; dst = hxi; }
    else                 { v = query[i]; dst = qry; }
    uint2 u = make_uint2(pack2h(__float2half(v.x), __float2half(v.y)),
                         pack2h(__float2half(v.z), __float2half(v.w)));
    *reinterpret_cast<uint2*>(dst + (size_t)i * 4) = u;
}

// ---------------------------------------------------------------------------
// K3: LSTM (fp16 gates in) -> hx,cx fp32 (outputs) + hx fp16
// ---------------------------------------------------------------------------
__global__ void k_lstm(const __half* __restrict__ gates, const float* __restrict__ cx_in,
                       float* __restrict__ hx_out, float* __restrict__ cx_out,
                       __half* __restrict__ hxo, int totalq) {
    int i = blockIdx.x * blockDim.x + threadIdx.x;
    if (i >= totalq) return;
    int b = i >> 6, j = (i & 63) << 2;
    const __half* g = gates + (size_t)b * 1024 + j;
    uint2 ui = *reinterpret_cast<const uint2*>(g);
    uint2 uf = *reinterpret_cast<const uint2*>(g + 256);
    uint2 ug = *reinterpret_cast<const uint2*>(g + 512);
    uint2 uo = *reinterpret_cast<const uint2*>(g + 768);
    auto up = [](uint2 u, float4& f) {
        __half2 lo = *reinterpret_cast<__half2*>(&u.x);
        __half2 hi = *reinterpret_cast<__half2*>(&u.y);
        f.x = __low2float(lo); f.y = __high2float(lo);
        f.z = __low2float(hi); f.w = __high2float(hi);
    };
    float4 gi, gf, gg, go;
    up(ui, gi); up(uf, gf); up(ug, gg); up(uo, go);
    float4 c0 = *reinterpret_cast<const float4*>(cx_in + (size_t)b * 256 + j);
    float4 ho, co;
    co.x = sigmoidf_(gf.x) * c0.x + sigmoidf_(gi.x) * tanhf(gg.x); ho.x = sigmoidf_(go.x) * tanhf(co.x);
    co.y = sigmoidf_(gf.y) * c0.y + sigmoidf_(gi.y) * tanhf(gg.y); ho.y = sigmoidf_(go.y) * tanhf(co.y);
    co.z = sigmoidf_(gf.z) * c0.z + sigmoidf_(gi.z) * tanhf(gg.z); ho.z = sigmoidf_(go.z) * tanhf(co.z);
    co.w = sigmoidf_(gf.w) * c0.w + sigmoidf_(gi.w) * tanhf(gg.w); ho.w = sigmoidf_(go.w) * tanhf(co.w);
    size_t o = (size_t)b * 256 + j;
    *reinterpret_cast<float4*>(hx_out + o) = ho;
    *reinterpret_cast<float4*>(cx_out + o) = co;
    uint2 u = make_uint2(pack2h(__float2half(ho.x), __float2half(ho.y)),
                         pack2h(__float2half(ho.z), __float2half(ho.w)));
    *reinterpret_cast<uint2*>(hxo + o) = u;
}

// ---------------------------------------------------------------------------
// MMA / cp.async helpers
// ---------------------------------------------------------------------------
__device__ __forceinline__ void ldm4(uint32_t* r, uint32_t addr) {
    asm volatile("ldmatrix.sync.aligned.m8n8.x4.shared.b16 {%0,%1,%2,%3}, [%4];"
                 : "=r"(r[0]), "=r"(r[1]), "=r"(r[2]), "=r"(r[3]) : "r"(addr));
}
__device__ __forceinline__ void mma16816(float* c, const uint32_t* a, uint32_t b0, uint32_t b1) {
    asm volatile(
        "mma.sync.aligned.m16n8k16.row.col.f32.f16.f16.f32 "
        "{%0,%1,%2,%3}, {%4,%5,%6,%7}, {%8,%9}, {%0,%1,%2,%3};"
        : "+f"(c[0]), "+f"(c[1]), "+f"(c[2]), "+f"(c[3])
        : "r"(a[0]), "r"(a[1]), "r"(a[2]), "r"(a[3]), "r"(b0), "r"(b1));
}
#define CPA16(dst, src) asm volatile("cp.async.cg.shared.global [%0], [%1], 16;\n" :: "r"(dst), "l"(src))
#define CPCOMMIT()      asm volatile("cp.async.commit_group;\n")
#define CPWAIT1()       asm volatile("cp.async.wait_group 1;\n")
#define CPWAIT0()       asm volatile("cp.async.wait_group 0;\n")

// ---------------------------------------------------------------------------
// GEMM: C = epi( sum_seg A_seg @ W_seg^T ), fp16 single pass, fp32 acc.
// 256 threads, 8 warps (4m x 2n), BM=128, K64 chunks (144B rows), 3-stage
// cp.async ring, one barrier/chunk. 2 CTAs/SM.
// EPI 0: +bias (split at nsplit), relu if ACT
// EPI 2: (+bias, relu) -> tanh(qout_h + v) * mlp_h[.,256+n]   (fp16 aux)
// EPI 4: (+bias split, relu) -> stage smem -> fused heads (pol/val) direct out
// EPI 5: dual-job: blockIdx.x < gx1 -> gates (+pre2 via idxp, fp16 Ch);
//        else qout job (Aq,Wq,Kq, +biasq, relu, fp16 Cqh)
// OUTM bit0: fp32 C; bit1: fp16 Ch.
// ---------------------------------------------------------------------------
template <int BN, int ACT, int EPI, int OUTM>
__global__ void __launch_bounds__(256, 2)
mma_gemm(int N,
         const __half* __restrict__ A0, int lda0,
         const __half* __restrict__ W0, int ldw0, int K0,
         const __half* __restrict__ A1, int lda1,
         const __half* __restrict__ W1, int ldw1, int K1,
         const float* __restrict__ bias, const float* __restrict__ bias2, int nsplit,
         const __half* __restrict__ auxh0, const __half* __restrict__ auxh1,
         const float* __restrict__ aux0,
         const int* __restrict__ idxp,
         float* __restrict__ C, __half* __restrict__ Ch, int ldc,
         const __half* __restrict__ Aq, int ldaq,
         const __half* __restrict__ Wq, int ldwq, int Kq,
         const float* __restrict__ biasq, __half* __restrict__ Cqh, int ldcq, int gx1,
         const float* __restrict__ hw_p, const float* __restrict__ hb_p,
         const float* __restrict__ hw_v, const float* __restrict__ hb_v,
         float* __restrict__ o_val, float* __restrict__ o_pol) {
    constexpr int WN      = BN / 2;                 // warp n-extent (2 warps in n)
    constexpr int NT8     = WN / 8;
    constexpr int N16T    = WN / 16;
    constexpr int SSTR    = 72;                     // halves/row: 64 data + 8 pad (144B)
    constexpr int A_BYTES = 128 * SSTR * 2;         // 18432
    constexpr int W_BYTES = BN * SSTR * 2;
    constexpr int STAGEB  = A_BYTES + W_BYTES;
    constexpr int WIT     = BN / 32;                // W cp.async iters

    extern __shared__ __half smem_dyn[];

    const int tid  = threadIdx.x;
    const int lane = tid & 31;
    const int wid  = tid >> 5;
    const int wm = wid & 3, wn = wid >> 2;          // 4 x 2 warps
    const int m0 = blockIdx.y * 128;

    const bool isq = (EPI == 5) && ((int)blockIdx.x >= gx1);
    const int n0 = (isq ? ((int)blockIdx.x - gx1) : (int)blockIdx.x) * BN;

    const __half* jA0 = isq ? Aq : A0;  const int jlda0 = isq ? ldaq : lda0;
    const __half* jW0 = isq ? Wq : W0;  const int jldw0 = isq ? ldwq : ldw0;
    const int jK0 = isq ? Kq : K0;
    const int jK1 = isq ? 0  : K1;

    const uint32_t smb = (uint32_t)__cvta_generic_to_shared(smem_dyn);

    float acc[2][NT8][4];
    #pragma unroll
    for (int i = 0; i < 2; i++)
        #pragma unroll
        for (int j = 0; j < NT8; j++)
            #pragma unroll
            for (int q = 0; q < 4; q++) acc[i][j][q] = 0.f;

    const int nc0 = jK0 >> 6;
    const int NC  = nc0 + (jK1 >> 6);

    auto issue = [&](int c) {
        const __half *A, *W;
        int lda, ldw, kc;
        if (c < nc0) { A = jA0; W = jW0; lda = jlda0; ldw = jldw0; kc = c << 6; }
        else         { A = A1;  W = W1;  lda = lda1;  ldw = ldw1;  kc = (c - nc0) << 6; }
        const uint32_t sb = smb + (uint32_t)(c % 3) * STAGEB;
        #pragma unroll
        for (int it = 0; it < 4; it++) {            // A: 128 rows x 8 segs
            int idx = tid + it * 256;
            int row = idx >> 3, seg = idx & 7;
            uint32_t off = (uint32_t)(row * SSTR + seg * 8) * 2;
            CPA16(sb + off, A + (size_t)(m0 + row) * lda + kc + seg * 8);
        }
        #pragma unroll
        for (int it = 0; it < WIT; it++) {          // W: BN rows x 8 segs
            int idx = tid + it * 256;
            int row = idx >> 3, seg = idx & 7;
            uint32_t off = (uint32_t)(row * SSTR + seg * 8) * 2;
            CPA16(sb + A_BYTES + off, W + (size_t)(n0 + row) * ldw + kc + seg * 8);
        }
    };

    issue(0); CPCOMMIT();
    if (NC > 1) { issue(1); CPCOMMIT(); }

    for (int c = 0; c < NC; c++) {
        if (c + 1 < NC) CPWAIT1(); else CPWAIT0();
        __syncthreads();
        if (c + 2 < NC) { issue(c + 2); CPCOMMIT(); }

        const uint32_t sb = smb + (uint32_t)(c % 3) * STAGEB;
        const uint32_t bA = sb;
        const uint32_t bW = sb + A_BYTES;

        #pragma unroll
        for (int kk = 0; kk < 64; kk += 16) {
            const int col = kk + ((lane >> 4) << 3);
            uint32_t a0[4], a1[4];
            {
                int row = wm * 32 + (lane & 15);
                ldm4(a0, bA + (uint32_t)(row * SSTR + col) * 2u);
                ldm4(a1, bA + (uint32_t)((row + 16) * SSTR + col) * 2u);
            }
            #pragma unroll
            for (int t = 0; t < N16T; t++) {
                uint32_t bh[4];
                int row = wn * WN + t * 16 + (lane & 15);
                ldm4(bh, bW + (uint32_t)(row * SSTR + col) * 2u);
                #pragma unroll
                for (int hs = 0; hs < 2; hs++) {
                    int nt = 2 * t + hs;
                    mma16816(acc[0][nt], a0, bh[hs], bh[2 + hs]);
                    mma16816(acc[1][nt], a1, bh[hs], bh[2 + hs]);
                }
            }
        }
    }

    if (EPI == 5) {
        #pragma unroll
        for (int mt = 0; mt < 2; mt++) {
            int r0 = m0 + wm * 32 + mt * 16 + (lane >> 2);
            int r1 = r0 + 8;
            int ib0 = 0, ib1 = 0;
            if (!isq) { ib0 = idxp[r0]; ib1 = idxp[r1]; }
            #pragma unroll
            for (int nt = 0; nt < NT8; nt++) {
                int cc = n0 + wn * WN + nt * 8 + ((lane & 3) << 1);
                #pragma unroll
                for (int p = 0; p < 2; p++) {
                    int r  = p ? r1 : r0;
                    float x = acc[mt][nt][2 * p];
                    float y = acc[mt][nt][2 * p + 1];
                    if (isq) {
                        x = fmaxf(x + biasq[cc], 0.f);
                        y = fmaxf(y + biasq[cc + 1], 0.f);
                        *reinterpret_cast<uint32_t*>(&Cqh[(size_t)r * ldcq + cc]) =
                            pack2h(__float2half(x), __float2half(y));
                    } else {
                        int ib = p ? ib1 : ib0;
                        x += aux0[(size_t)ib * 1024 + cc];
                        y += aux0[(size_t)ib * 1024 + cc + 1];
                        *reinterpret_cast<uint32_t*>(&Ch[(size_t)r * ldc + cc]) =
                            pack2h(__float2half(x), __float2half(y));
                    }
                }
            }
        }
        return;
    }

    if (EPI == 4) {
        // ---- fused pol2/val2 + heads epilogue (n0 == 0, N == 96) ----
        __syncthreads();                            // pipeline smem reusable
        float* sf = reinterpret_cast<float*>(smem_dyn);   // stride 98 floats
        #pragma unroll
        for (int mt = 0; mt < 2; mt++) {
            int rl0 = wm * 32 + mt * 16 + (lane >> 2);
            #pragma unroll
            for (int nt = 0; nt < NT8; nt++) {
                int cc = wn * WN + nt * 8 + ((lane & 3) << 1);
                float bb0 = (cc < nsplit) ? bias[cc] : bias2[cc - nsplit];
                float bb1 = (cc < nsplit) ? bias[cc + 1] : bias2[cc + 1 - nsplit];
                #pragma unroll
                for (int p = 0; p < 2; p++) {
                    int rl = rl0 + p * 8;
                    float x = fmaxf(acc[mt][nt][2 * p] + bb0, 0.f);
                    float y = fmaxf(acc[mt][nt][2 * p + 1] + bb1, 0.f);
                    *reinterpret_cast<float2*>(&sf[rl * 98 + cc]) = make_float2(x, y);
                }
            }
        }
        __syncthreads();
        if (tid < 128) {
            int b = m0 + tid;
            const float* row = &sf[tid * 98];
            float p0 = hb_p[0], p1 = hb_p[1], p2 = hb_p[2];
            #pragma unroll
            for (int k = 0; k < 64; k++) {
                float xv = row[k];
                p0 = fmaf(xv, hw_p[k], p0);
                p1 = fmaf(xv, hw_p[64 + k], p1);
                p2 = fmaf(xv, hw_p[128 + k], p2);
            }
            o_pol[(size_t)b * 3 + 0] = p0;
            o_pol[(size_t)b * 3 + 1] = p1;
            o_pol[(size_t)b * 3 + 2] = p2;
            float v = hb_v[0];
            #pragma unroll
            for (int k = 0; k < 32; k++) v = fmaf(row[64 + k], hw_v[k], v);
            o_val[b] = v;
        }
        return;
    }

    // ---- standard epilogue (EPI 0 / 2) ----
    #pragma unroll
    for (int mt = 0; mt < 2; mt++) {
        int r0 = m0 + wm * 32 + mt * 16 + (lane >> 2);
        int r1 = r0 + 8;
        #pragma unroll
        for (int nt = 0; nt < NT8; nt++) {
            int cc = n0 + wn * WN + nt * 8 + ((lane & 3) << 1);
            if (cc < N) {
                float bb0 = 0.f, bb1 = 0.f;
                if (bias) {
                    if (cc < nsplit) { bb0 = bias[cc]; bb1 = bias[cc + 1]; }
                    else             { bb0 = bias2[cc - nsplit]; bb1 = bias2[cc + 1 - nsplit]; }
                }
                #pragma unroll
                for (int p = 0; p < 2; p++) {
                    int r = p ? r1 : r0;
                    float x = acc[mt][nt][2 * p] + bb0;
                    float y = acc[mt][nt][2 * p + 1] + bb1;
                    if (ACT) { x = fmaxf(x, 0.f); y = fmaxf(y, 0.f); }
                    if (EPI == 2) {
                        __half2 q2 = *reinterpret_cast<const __half2*>(&auxh0[(size_t)r * 256 + cc]);
                        __half2 v2 = *reinterpret_cast<const __half2*>(&auxh1[(size_t)r * 512 + 256 + cc]);
                        x = tanhf(__low2float(q2) + x)  * __low2float(v2);
                        y = tanhf(__high2float(q2) + y) * __high2float(v2);
                    }
                    size_t o = (size_t)r * ldc + cc;
                    if (OUTM & 1)
                        *reinterpret_cast<float2*>(&C[o]) = make_float2(x, y);
                    if (OUTM & 2)
                        *reinterpret_cast<uint32_t*>(Ch + o) = pack2h(__float2half(x), __float2half(y));
                }
            }
        }
    }
}

// ---------------------------------------------------------------------------
// host launcher
// ---------------------------------------------------------------------------
extern "C" void kernel_launch(void* const* d_in, const int* in_sizes, int n_in,
                              void* d_out, int out_size) {
    const float* img   = (const float*)d_in[0];
    const int*   idx   = (const int*)  d_in[1];
    const float* hx_in = (const float*)d_in[2];
    const float* cx_in = (const float*)d_in[3];
    const float* query = (const float*)d_in[4];
    const float* emb   = (const float*)d_in[5];
    const float* w_ta  = (const float*)d_in[6];
    const float* b_ta  = (const float*)d_in[7];
    const float* w_ih  = (const float*)d_in[8];
    const float* w_hh  = (const float*)d_in[9];
    const float* b_ih  = (const float*)d_in[10];
    const float* b_hh  = (const float*)d_in[11];
    const float* w_q   = (const float*)d_in[12];
    const float* b_q   = (const float*)d_in[13];
    const float* w_k   = (const float*)d_in[14];
    const float* b_k   = (const float*)d_in[15];
    const float* w_ba  = (const float*)d_in[16];
    const float* b_ba  = (const float*)d_in[17];
    const float* w_at  = (const float*)d_in[18];
    const float* b_at  = (const float*)d_in[19];
    const float* w_p1  = (const float*)d_in[20];
    const float* b_p1  = (const float*)d_in[21];
    const float* w_p2  = (const float*)d_in[22];
    const float* b_p2  = (const float*)d_in[23];
    const float* w_p   = (const float*)d_in[24];
    const float* b_p   = (const float*)d_in[25];
    const float* w_v1  = (const float*)d_in[26];
    const float* b_v1  = (const float*)d_in[27];
    const float* w_v2  = (const float*)d_in[28];
    const float* b_v2  = (const float*)d_in[29];
    const float* w_v   = (const float*)d_in[30];
    const float* b_v   = (const float*)d_in[31];

    const int B = in_sizes[0] / 256;  // 32768

    float* F = nullptr;
    cudaGetSymbolAddress((void**)&F, g_f32);
    __half* HF = nullptr;
    cudaGetSymbolAddress((void**)&HF, g_hf);

    float* tab   = F + F_TAB;
    float* pre2  = F + F_PRE2;

    float* out   = (float*)d_out;
    float* o_val = out;
    float* o_pol = out + (size_t)B;
    float* o_hx  = out + (size_t)B * 4;
    float* o_cx  = o_hx + (size_t)B * 256;

    // smem: 3 stages; stage = 18432 + BN*144
    const int SM128 = 3 * (18432 + 128 * 144);  // 110592
    const int SM96  = 3 * (18432 + 96 * 144);   // 96768
    const int SM64  = 3 * (18432 + 64 * 144);   // 82944
    cudaFuncSetAttribute(mma_gemm<128, 0, 5, 1>, cudaFuncAttributeMaxDynamicSharedMemorySize, SM128);
    cudaFuncSetAttribute(mma_gemm<128, 1, 0, 2>, cudaFuncAttributeMaxDynamicSharedMemorySize, SM128);
    cudaFuncSetAttribute(mma_gemm<128, 1, 2, 2>, cudaFuncAttributeMaxDynamicSharedMemorySize, SM128);
    cudaFuncSetAttribute(mma_gemm<64, 1, 0, 2>,  cudaFuncAttributeMaxDynamicSharedMemorySize, SM64);
    cudaFuncSetAttribute(mma_gemm<96, 1, 4, 0>,  cudaFuncAttributeMaxDynamicSharedMemorySize, SM96);

    // K0: tables
    k0_tables<<<1, 1024>>>(emb, w_ta, b_ta, w_ih, b_ih, b_hh, tab, pre2);

    // fused weight convert (9 segments, one launch)
    {
        WAll d;
        auto seg = [&](int i, const float* src, int srcld, int cols, int rows, int padrows,
                       size_t hoff) {
            d.s[i] = WSeg{src, nullptr, srcld, cols, rows, padrows * cols, 0, (long long)hoff};
        };
        seg(0, w_ih, 512, 256, 1024, 1024, H_WIH);
        seg(1, w_hh, 256, 256, 1024, 1024, H_WHH);
        seg(2, w_ba, 512, 512, 512, 512, H_WBA);
        seg(3, w_q,  256, 256, 256, 256, H_WQ);
        seg(4, w_k,  256, 256, 256, 256, H_WK);
        seg(5, w_at, 512, 512, 256, 256, H_WAT);
        seg(6, w_p1, 256, 256, 128, 128, H_WPV);
        seg(7, w_v1, 256, 256, 64, 64, H_WPV + 128 * 256);
        d.s[8] = WSeg{w_p2, w_v2, 0, 0, 0, 128 * 192, 2, (long long)H_WC};
        int total = 0;
        for (int i = 0; i < 9; i++) total += d.s[i].total;
        k_wsplit_all<<<(total + 255) / 256, 256>>>(d, HF);
    }

    // fused prep
    k_prep<<<(3 * B * 64 + 255) / 256, 256>>>(
        (const float4*)img, idx, tab, (const float4*)hx_in, (const float4*)query,
        HF + H_FUS, HF + H_HXI, HF + H_QRY, B * 64);

    // K2+K5 merged: gates GEMM (x<8, fp16 out) + qout GEMM (x>=8, fp16 out)
    mma_gemm<128, 0, 5, 1><<<dim3(10, B / 128), 256, SM128>>>(
        1024,
        HF + H_FUS, 256, HF + H_WIH, 256, 256,
        HF + H_HXI, 256, HF + H_WHH, 256, 256,
        nullptr, nullptr, 1 << 30, nullptr, nullptr, pre2, idx,
        nullptr, HF + H_GATES, 1024,
        HF + H_QRY, 256, HF + H_WQ, 256, 256, b_q, HF + H_QOUT, 256, 8,
        nullptr, nullptr, nullptr, nullptr, nullptr, nullptr);

    // K3: LSTM (fp16 gates)
    k_lstm<<<(B * 64 + 255) / 256, 256>>>(HF + H_GATES, cx_in, o_hx, o_cx, HF + H_HXO, B * 64);

    // K4: mlp = relu([fus|hx] @ w_ba^T + b_ba)  (fp16 only)
    mma_gemm<128, 1, 0, 2><<<dim3(4, B / 128), 256, SM128>>>(
        512,
        HF + H_FUS, 256, HF + H_WBA, 512, 256,
        HF + H_HXO, 256, HF + H_WBA + 256, 512, 256,
        b_ba, nullptr, 1 << 30, nullptr, nullptr, nullptr, nullptr, nullptr, HF + H_MLP, 512,
        nullptr, 0, nullptr, 0, 0, nullptr, nullptr, 0, 0,
        nullptr, nullptr, nullptr, nullptr, nullptr, nullptr);

    // K6: avec = tanh(qout_h + relu(key @ w_k^T + b_k)) * mlp_h[.,256+n]  (fp16)
    mma_gemm<128, 1, 2, 2><<<dim3(2, B / 128), 256, SM128>>>(
        256,
        HF + H_MLP, 512, HF + H_WK, 256, 256,
        nullptr, 0, nullptr, 0, 0,
        b_k, nullptr, 1 << 30, HF + H_QOUT, HF + H_MLP, nullptr, nullptr,
        nullptr, HF + H_AVEC, 256,
        nullptr, 0, nullptr, 0, 0, nullptr, nullptr, 0, 0,
        nullptr, nullptr, nullptr, nullptr, nullptr, nullptr);

    // K7: attnw = relu([avec|hx] @ w_at^T + b_at)  (fp16)
    mma_gemm<128, 1, 0, 2><<<dim3(2, B / 128), 256, SM128>>>(
        256,
        HF + H_AVEC, 256, HF + H_WAT, 512, 256,
        HF + H_HXO, 256, HF + H_WAT + 256, 512, 256,
        b_at, nullptr, 1 << 30, nullptr, nullptr, nullptr, nullptr, nullptr, HF + H_ATT, 256,
        nullptr, 0, nullptr, 0, 0, nullptr, nullptr, 0, 0,
        nullptr, nullptr, nullptr, nullptr, nullptr, nullptr);

    // K8: [pol1|val1] = relu(attnw @ [w_p1;w_v1]^T + [b_p1;b_v1])  N=192 (fp16)
    mma_gemm<64, 1, 0, 2><<<dim3(3, B / 128), 256, SM64>>>(
        192,
        HF + H_ATT, 256, HF + H_WPV, 256, 256,
        nullptr, 0, nullptr, 0, 0,
        b_p1, b_v1, 128, nullptr, nullptr, nullptr, nullptr, nullptr, HF + H_P1V1, 192,
        nullptr, 0, nullptr, 0, 0, nullptr, nullptr, 0, 0,
        nullptr, nullptr, nullptr, nullptr, nullptr, nullptr);

    // K9 fused with heads: [pol2|val2] GEMM (N=96, blockdiag) -> pol/val outputs
    mma_gemm<96, 1, 4, 0><<<dim3(1, B / 128), 256, SM96>>>(
        96,
        HF + H_P1V1, 192, HF + H_WC, 192, 192,
        nullptr, 0, nullptr, 0, 0,
        b_p2, b_v2, 64, nullptr, nullptr, nullptr, nullptr, nullptr, nullptr, 96,
        nullptr, 0, nullptr, 0, 0, nullptr, nullptr, 0, 0,
        w_p, b_p, w_v, b_v, o_val, o_pol);
}

// round 16
// speedup vs baseline: 1.1401x; 1.0039x over previous
#include <cuda_runtime.h>
#include <cuda_fp16.h>
#include <cstdint>
#include <math.h>

// ---------------------------------------------------------------------------
// Actor_Critic — single-pass fp16 MMA pipeline.
// 256-thread GEMM CTAs, K64 chunks, 3-stage cp.async ring, one barrier/chunk,
// 2 CTAs/SM. Warp K-phase staggering inside the chunk loop to de-align
// ldmatrix/MMA phases across warps. qout merged into gates launch; gates fp16;
// K9 GEMM fused with final heads.
// ---------------------------------------------------------------------------

constexpr size_t S_B = 32768;

// fp32 scratch
constexpr size_t F_TAB   = 0;
constexpr size_t F_PRE2  = 1024;
constexpr size_t F_END   = F_PRE2 + 4096;
__device__ float g_f32[F_END];

// fp16 scratch
constexpr size_t H_WIH   = 0;                        // 1024x256
constexpr size_t H_WHH   = H_WIH   + 262144;         // 1024x256
constexpr size_t H_WBA   = H_WHH   + 262144;         // 512x512
constexpr size_t H_WQ    = H_WBA   + 262144;         // 256x256
constexpr size_t H_WK    = H_WQ    + 65536;          // 256x256
constexpr size_t H_WAT   = H_WK    + 65536;          // 256x512
constexpr size_t H_WPV   = H_WAT   + 131072;         // 192x256
constexpr size_t H_WC    = H_WPV   + 49152;          // 128x192 block-diag
constexpr size_t H_FUS   = H_WC    + 24576;          // B*256
constexpr size_t H_HXI   = H_FUS   + S_B * 256;
constexpr size_t H_QRY   = H_HXI   + S_B * 256;
constexpr size_t H_HXO   = H_QRY   + S_B * 256;
constexpr size_t H_MLP   = H_HXO   + S_B * 256;      // B*512
constexpr size_t H_AVEC  = H_MLP   + S_B * 512;
constexpr size_t H_ATT   = H_AVEC  + S_B * 256;
constexpr size_t H_P1V1  = H_ATT   + S_B * 256;      // B*192
constexpr size_t H_QOUT  = H_P1V1  + S_B * 192;      // B*256 (fp16 qout)
constexpr size_t H_GATES = H_QOUT  + S_B * 256;      // B*1024 (fp16 gates)
constexpr size_t H_END   = H_GATES + S_B * 1024;
__device__ __half g_hf[H_END];

__device__ __forceinline__ float sigmoidf_(float x) { return 1.f / (1.f + expf(-x)); }
__device__ __forceinline__ uint32_t pack2h(__half a, __half b) {
    return (uint32_t)__half_as_ushort(a) | ((uint32_t)__half_as_ushort(b) << 16);
}

// ---------------------------------------------------------------------------
// K0: gated_att table (4x256) + pre2 table (4x1024)
// ---------------------------------------------------------------------------
__global__ void k0_tables(const float* __restrict__ emb,  const float* __restrict__ w_ta,
                          const float* __restrict__ b_ta, const float* __restrict__ w_ih,
                          const float* __restrict__ b_ih, const float* __restrict__ b_hh,
                          float* __restrict__ tab, float* __restrict__ pre2) {
    int t = threadIdx.x;  // 1024
    {
        int r = t >> 8, j = t & 255;
        float s = b_ta[j];
        #pragma unroll
        for (int k = 0; k < 25; k++) s += emb[r * 25 + k] * w_ta[j * 25 + k];
        tab[t] = sigmoidf_(s);
    }
    __syncthreads();
    {
        int j = t;
        const float* wrow = &w_ih[(size_t)j * 512 + 256];
        float base = b_ih[j] + b_hh[j];
        for (int r = 0; r < 4; r++) {
            const float* tr = &tab[r * 256];
            float s = base;
            for (int k = 0; k < 256; k++) s += tr[k] * wrow[k];
            pre2[r * 1024 + j] = s;
        }
    }
}

// ---------------------------------------------------------------------------
// fused weight convert to fp16. mode 0: normal; mode 2: p2/v2 block-diag.
// ---------------------------------------------------------------------------
struct WSeg { const float* src; const float* src2; int srcld, cols, rows, total, mode;
              long long hoff; };
struct WAll { WSeg s[9]; };

__global__ void k_wsplit_all(WAll d, __half* __restrict__ base) {
    int i = blockIdx.x * blockDim.x + threadIdx.x;
    #pragma unroll
    for (int s = 0; s < 9; s++) {
        const WSeg& g = d.s[s];
        if (i < g.total) {
            float v;
            if (g.mode == 0) {
                int r = i / g.cols, c = i - r * g.cols;
                v = (r < g.rows) ? g.src[(size_t)r * g.srcld + c] : 0.f;
            } else {
                int r = i / 192, c = i - r * 192;
                if (r < 64)       v = (c < 128) ? g.src[r * 128 + c] : 0.f;
                else if (c >= 128 && r - 64 < 32) v = g.src2[(r - 64) * 64 + (c - 128)];
                else              v = 0.f;
            }
            base[g.hoff + i] = __float2half(v);
            return;
        }
        i -= g.total;
    }
}

// ---------------------------------------------------------------------------
// fused prep: region 0 fusion(img*tab[idx]); 1: round hx_in; 2: round query
// ---------------------------------------------------------------------------
__global__ void k_prep(const float4* __restrict__ img, const int* __restrict__ idx,
                       const float* __restrict__ tab,
                       const float4* __restrict__ hx_in, const float4* __restrict__ query,
                       __half* __restrict__ fus, __half* __restrict__ hxi,
                       __half* __restrict__ qry, int nq) {
    int i = blockIdx.x * blockDim.x + threadIdx.x;
    int reg = 0;
    if (i >= nq) { i -= nq; reg = 1; }
    if (i >= nq) { i -= nq; reg = 2; }
    if (i >= nq) return;
    float4 v;
    __half* dst;
    if (reg == 0) {
        int b = i >> 6, j4 = (i & 63) << 2;
        float4 g = *reinterpret_cast<const float4*>(tab + idx[b] * 256 + j4);
        v = img[i];
        v.x *= g.x; v.y *= g.y; v.z *= g.z; v.w *= g.w;
        dst = fus;
    } else if (reg == 1) { v = hx_in[i]; dst = hxi; }
    else                 { v = query[i]; dst = qry; }
    uint2 u = make_uint2(pack2h(__float2half(v.x), __float2half(v.y)),
                         pack2h(__float2half(v.z), __float2half(v.w)));
    *reinterpret_cast<uint2*>(dst + (size_t)i * 4) = u;
}

// ---------------------------------------------------------------------------
// K3: LSTM (fp16 gates in) -> hx,cx fp32 (outputs) + hx fp16
// ---------------------------------------------------------------------------
__global__ void k_lstm(const __half* __restrict__ gates, const float* __restrict__ cx_in,
                       float* __restrict__ hx_out, float* __restrict__ cx_out,
                       __half* __restrict__ hxo, int totalq) {
    int i = blockIdx.x * blockDim.x + threadIdx.x;
    if (i >= totalq) return;
    int b = i >> 6, j = (i & 63) << 2;
    const __half* g = gates + (size_t)b * 1024 + j;
    uint2 ui = *reinterpret_cast<const uint2*>(g);
    uint2 uf = *reinterpret_cast<const uint2*>(g + 256);
    uint2 ug = *reinterpret_cast<const uint2*>(g + 512);
    uint2 uo = *reinterpret_cast<const uint2*>(g + 768);
    auto up = [](uint2 u, float4& f) {
        __half2 lo = *reinterpret_cast<__half2*>(&u.x);
        __half2 hi = *reinterpret_cast<__half2*>(&u.y);
        f.x = __low2float(lo); f.y = __high2float(lo);
        f.z = __low2float(hi); f.w = __high2float(hi);
    };
    float4 gi, gf, gg, go;
    up(ui, gi); up(uf, gf); up(ug, gg); up(uo, go);
    float4 c0 = *reinterpret_cast<const float4*>(cx_in + (size_t)b * 256 + j);
    float4 ho, co;
    co.x = sigmoidf_(gf.x) * c0.x + sigmoidf_(gi.x) * tanhf(gg.x); ho.x = sigmoidf_(go.x) * tanhf(co.x);
    co.y = sigmoidf_(gf.y) * c0.y + sigmoidf_(gi.y) * tanhf(gg.y); ho.y = sigmoidf_(go.y) * tanhf(co.y);
    co.z = sigmoidf_(gf.z) * c0.z + sigmoidf_(gi.z) * tanhf(gg.z); ho.z = sigmoidf_(go.z) * tanhf(co.z);
    co.w = sigmoidf_(gf.w) * c0.w + sigmoidf_(gi.w) * tanhf(gg.w); ho.w = sigmoidf_(go.w) * tanhf(co.w);
    size_t o = (size_t)b * 256 + j;
    *reinterpret_cast<float4*>(hx_out + o) = ho;
    *reinterpret_cast<float4*>(cx_out + o) = co;
    uint2 u = make_uint2(pack2h(__float2half(ho.x), __float2half(ho.y)),
                         pack2h(__float2half(ho.z), __float2half(ho.w)));
    *reinterpret_cast<uint2*>(hxo + o) = u;
}

// ---------------------------------------------------------------------------
// MMA / cp.async helpers
// ---------------------------------------------------------------------------
__device__ __forceinline__ void ldm4(uint32_t* r, uint32_t addr) {
    asm volatile("ldmatrix.sync.aligned.m8n8.x4.shared.b16 {%0,%1,%2,%3}, [%4];"
                 : "=r"(r[0]), "=r"(r[1]), "=r"(r[2]), "=r"(r[3]) : "r"(addr));
}
__device__ __forceinline__ void mma16816(float* c, const uint32_t* a, uint32_t b0, uint32_t b1) {
    asm volatile(
        "mma.sync.aligned.m16n8k16.row.col.f32.f16.f16.f32 "
        "{%0,%1,%2,%3}, {%4,%5,%6,%7}, {%8,%9}, {%0,%1,%2,%3};"
        : "+f"(c[0]), "+f"(c[1]), "+f"(c[2]), "+f"(c[3])
        : "r"(a[0]), "r"(a[1]), "r"(a[2]), "r"(a[3]), "r"(b0), "r"(b1));
}
#define CPA16(dst, src) asm volatile("cp.async.cg.shared.global [%0], [%1], 16;\n" :: "r"(dst), "l"(src))
#define CPCOMMIT()      asm volatile("cp.async.commit_group;\n")
#define CPWAIT1()       asm volatile("cp.async.wait_group 1;\n")
#define CPWAIT0()       asm volatile("cp.async.wait_group 0;\n")

// ---------------------------------------------------------------------------
// GEMM: C = epi( sum_seg A_seg @ W_seg^T ), fp16 single pass, fp32 acc.
// 256 threads, 8 warps (4m x 2n), BM=128, K64 chunks (144B rows), 3-stage
// cp.async ring, one barrier/chunk, warp K-phase stagger. 2 CTAs/SM.
// EPI 0: +bias (split at nsplit), relu if ACT
// EPI 2: (+bias, relu) -> tanh(qout_h + v) * mlp_h[.,256+n]   (fp16 aux)
// EPI 4: (+bias split, relu) -> stage smem -> fused heads (pol/val) direct out
// EPI 5: dual-job: blockIdx.x < gx1 -> gates (+pre2 via idxp, fp16 Ch);
//        else qout job (Aq,Wq,Kq, +biasq, relu, fp16 Cqh)
// OUTM bit0: fp32 C; bit1: fp16 Ch.
// ---------------------------------------------------------------------------
template <int BN, int ACT, int EPI, int OUTM>
__global__ void __launch_bounds__(256, 2)
mma_gemm(int N,
         const __half* __restrict__ A0, int lda0,
         const __half* __restrict__ W0, int ldw0, int K0,
         const __half* __restrict__ A1, int lda1,
         const __half* __restrict__ W1, int ldw1, int K1,
         const float* __restrict__ bias, const float* __restrict__ bias2, int nsplit,
         const __half* __restrict__ auxh0, const __half* __restrict__ auxh1,
         const float* __restrict__ aux0,
         const int* __restrict__ idxp,
         float* __restrict__ C, __half* __restrict__ Ch, int ldc,
         const __half* __restrict__ Aq, int ldaq,
         const __half* __restrict__ Wq, int ldwq, int Kq,
         const float* __restrict__ biasq, __half* __restrict__ Cqh, int ldcq, int gx1,
         const float* __restrict__ hw_p, const float* __restrict__ hb_p,
         const float* __restrict__ hw_v, const float* __restrict__ hb_v,
         float* __restrict__ o_val, float* __restrict__ o_pol) {
    constexpr int WN      = BN / 2;                 // warp n-extent (2 warps in n)
    constexpr int NT8     = WN / 8;
    constexpr int N16T    = WN / 16;
    constexpr int SSTR    = 72;                     // halves/row: 64 data + 8 pad (144B)
    constexpr int A_BYTES = 128 * SSTR * 2;         // 18432
    constexpr int W_BYTES = BN * SSTR * 2;
    constexpr int STAGEB  = A_BYTES + W_BYTES;
    constexpr int WIT     = BN / 32;                // W cp.async iters

    extern __shared__ __half smem_dyn[];

    const int tid  = threadIdx.x;
    const int lane = tid & 31;
    const int wid  = tid >> 5;
    const int wm = wid & 3, wn = wid >> 2;          // 4 x 2 warps
    const int m0 = blockIdx.y * 128;

    const bool isq = (EPI == 5) && ((int)blockIdx.x >= gx1);
    const int n0 = (isq ? ((int)blockIdx.x - gx1) : (int)blockIdx.x) * BN;

    const __half* jA0 = isq ? Aq : A0;  const int jlda0 = isq ? ldaq : lda0;
    const __half* jW0 = isq ? Wq : W0;  const int jldw0 = isq ? ldwq : ldw0;
    const int jK0 = isq ? Kq : K0;
    const int jK1 = isq ? 0  : K1;

    const uint32_t smb = (uint32_t)__cvta_generic_to_shared(smem_dyn);

    float acc[2][NT8][4];
    #pragma unroll
    for (int i = 0; i < 2; i++)
        #pragma unroll
        for (int j = 0; j < NT8; j++)
            #pragma unroll
            for (int q = 0; q < 4; q++) acc[i][j][q] = 0.f;

    const int nc0 = jK0 >> 6;
    const int NC  = nc0 + (jK1 >> 6);

    auto issue = [&](int c) {
        const __half *A, *W;
        int lda, ldw, kc;
        if (c < nc0) { A = jA0; W = jW0; lda = jlda0; ldw = jldw0; kc = c << 6; }
        else         { A = A1;  W = W1;  lda = lda1;  ldw = ldw1;  kc = (c - nc0) << 6; }
        const uint32_t sb = smb + (uint32_t)(c % 3) * STAGEB;
        #pragma unroll
        for (int it = 0; it < 4; it++) {            // A: 128 rows x 8 segs
            int idx = tid + it * 256;
            int row = idx >> 3, seg = idx & 7;
            uint32_t off = (uint32_t)(row * SSTR + seg * 8) * 2;
            CPA16(sb + off, A + (size_t)(m0 + row) * lda + kc + seg * 8);
        }
        #pragma unroll
        for (int it = 0; it < WIT; it++) {          // W: BN rows x 8 segs
            int idx = tid + it * 256;
            int row = idx >> 3, seg = idx & 7;
            uint32_t off = (uint32_t)(row * SSTR + seg * 8) * 2;
            CPA16(sb + A_BYTES + off, W + (size_t)(n0 + row) * ldw + kc + seg * 8);
        }
    };

    issue(0); CPCOMMIT();
    if (NC > 1) { issue(1); CPCOMMIT(); }

    for (int c = 0; c < NC; c++) {
        if (c + 1 < NC) CPWAIT1(); else CPWAIT0();
        __syncthreads();
        if (c + 2 < NC) { issue(c + 2); CPCOMMIT(); }

        const uint32_t sb = smb + (uint32_t)(c % 3) * STAGEB;
        const uint32_t bA = sb;
        const uint32_t bW = sb + A_BYTES;

        // K-phase stagger: warp wid starts at kk-slot (wid & 3); accumulation
        // order over kk differs per warp (commutative fp32 adds), acc indices
        // stay compile-time.
        #pragma unroll
        for (int kt = 0; kt < 4; kt++) {
            const int kk = (((kt + wid) & 3) << 4);
            const int col = kk + ((lane >> 4) << 3);
            uint32_t a0[4], a1[4];
            {
                int row = wm * 32 + (lane & 15);
                ldm4(a0, bA + (uint32_t)(row * SSTR + col) * 2u);
                ldm4(a1, bA + (uint32_t)((row + 16) * SSTR + col) * 2u);
            }
            #pragma unroll
            for (int t = 0; t < N16T; t++) {
                uint32_t bh[4];
                int row = wn * WN + t * 16 + (lane & 15);
                ldm4(bh, bW + (uint32_t)(row * SSTR + col) * 2u);
                #pragma unroll
                for (int hs = 0; hs < 2; hs++) {
                    int nt = 2 * t + hs;
                    mma16816(acc[0][nt], a0, bh[hs], bh[2 + hs]);
                    mma16816(acc[1][nt], a1, bh[hs], bh[2 + hs]);
                }
            }
        }
    }

    if (EPI == 5) {
        #pragma unroll
        for (int mt = 0; mt < 2; mt++) {
            int r0 = m0 + wm * 32 + mt * 16 + (lane >> 2);
            int r1 = r0 + 8;
            int ib0 = 0, ib1 = 0;
            if (!isq) { ib0 = idxp[r0]; ib1 = idxp[r1]; }
            #pragma unroll
            for (int nt = 0; nt < NT8; nt++) {
                int cc = n0 + wn * WN + nt * 8 + ((lane & 3) << 1);
                #pragma unroll
                for (int p = 0; p < 2; p++) {
                    int r  = p ? r1 : r0;
                    float x = acc[mt][nt][2 * p];
                    float y = acc[mt][nt][2 * p + 1];
                    if (isq) {
                        x = fmaxf(x + biasq[cc], 0.f);
                        y = fmaxf(y + biasq[cc + 1], 0.f);
                        *reinterpret_cast<uint32_t*>(&Cqh[(size_t)r * ldcq + cc]) =
                            pack2h(__float2half(x), __float2half(y));
                    } else {
                        int ib = p ? ib1 : ib0;
                        x += aux0[(size_t)ib * 1024 + cc];
                        y += aux0[(size_t)ib * 1024 + cc + 1];
                        *reinterpret_cast<uint32_t*>(&Ch[(size_t)r * ldc + cc]) =
                            pack2h(__float2half(x), __float2half(y));
                    }
                }
            }
        }
        return;
    }

    if (EPI == 4) {
        // ---- fused pol2/val2 + heads epilogue (n0 == 0, N == 96) ----
        __syncthreads();                            // pipeline smem reusable
        float* sf = reinterpret_cast<float*>(smem_dyn);   // stride 98 floats
        #pragma unroll
        for (int mt = 0; mt < 2; mt++) {
            int rl0 = wm * 32 + mt * 16 + (lane >> 2);
            #pragma unroll
            for (int nt = 0; nt < NT8; nt++) {
                int cc = wn * WN + nt * 8 + ((lane & 3) << 1);
                float bb0 = (cc < nsplit) ? bias[cc] : bias2[cc - nsplit];
                float bb1 = (cc < nsplit) ? bias[cc + 1] : bias2[cc + 1 - nsplit];
                #pragma unroll
                for (int p = 0; p < 2; p++) {
                    int rl = rl0 + p * 8;
                    float x = fmaxf(acc[mt][nt][2 * p] + bb0, 0.f);
                    float y = fmaxf(acc[mt][nt][2 * p + 1] + bb1, 0.f);
                    *reinterpret_cast<float2*>(&sf[rl * 98 + cc]) = make_float2(x, y);
                }
            }
        }
        __syncthreads();
        if (tid < 128) {
            int b = m0 + tid;
            const float* row = &sf[tid * 98];
            float p0 = hb_p[0], p1 = hb_p[1], p2 = hb_p[2];
            #pragma unroll
            for (int k = 0; k < 64; k++) {
                float xv = row[k];
                p0 = fmaf(xv, hw_p[k], p0);
                p1 = fmaf(xv, hw_p[64 + k], p1);
                p2 = fmaf(xv, hw_p[128 + k], p2);
            }
            o_pol[(size_t)b * 3 + 0] = p0;
            o_pol[(size_t)b * 3 + 1] = p1;
            o_pol[(size_t)b * 3 + 2] = p2;
            float v = hb_v[0];
            #pragma unroll
            for (int k = 0; k < 32; k++) v = fmaf(row[64 + k], hw_v[k], v);
            o_val[b] = v;
        }
        return;
    }

    // ---- standard epilogue (EPI 0 / 2) ----
    #pragma unroll
    for (int mt = 0; mt < 2; mt++) {
        int r0 = m0 + wm * 32 + mt * 16 + (lane >> 2);
        int r1 = r0 + 8;
        #pragma unroll
        for (int nt = 0; nt < NT8; nt++) {
            int cc = n0 + wn * WN + nt * 8 + ((lane & 3) << 1);
            if (cc < N) {
                float bb0 = 0.f, bb1 = 0.f;
                if (bias) {
                    if (cc < nsplit) { bb0 = bias[cc]; bb1 = bias[cc + 1]; }
                    else             { bb0 = bias2[cc - nsplit]; bb1 = bias2[cc + 1 - nsplit]; }
                }
                #pragma unroll
                for (int p = 0; p < 2; p++) {
                    int r = p ? r1 : r0;
                    float x = acc[mt][nt][2 * p] + bb0;
                    float y = acc[mt][nt][2 * p + 1] + bb1;
                    if (ACT) { x = fmaxf(x, 0.f); y = fmaxf(y, 0.f); }
                    if (EPI == 2) {
                        __half2 q2 = *reinterpret_cast<const __half2*>(&auxh0[(size_t)r * 256 + cc]);
                        __half2 v2 = *reinterpret_cast<const __half2*>(&auxh1[(size_t)r * 512 + 256 + cc]);
                        x = tanhf(__low2float(q2) + x)  * __low2float(v2);
                        y = tanhf(__high2float(q2) + y) * __high2float(v2);
                    }
                    size_t o = (size_t)r * ldc + cc;
                    if (OUTM & 1)
                        *reinterpret_cast<float2*>(&C[o]) = make_float2(x, y);
                    if (OUTM & 2)
                        *reinterpret_cast<uint32_t*>(Ch + o) = pack2h(__float2half(x), __float2half(y));
                }
            }
        }
    }
}

// ---------------------------------------------------------------------------
// host launcher
// ---------------------------------------------------------------------------
extern "C" void kernel_launch(void* const* d_in, const int* in_sizes, int n_in,
                              void* d_out, int out_size) {
    const float* img   = (const float*)d_in[0];
    const int*   idx   = (const int*)  d_in[1];
    const float* hx_in = (const float*)d_in[2];
    const float* cx_in = (const float*)d_in[3];
    const float* query = (const float*)d_in[4];
    const float* emb   = (const float*)d_in[5];
    const float* w_ta  = (const float*)d_in[6];
    const float* b_ta  = (const float*)d_in[7];
    const float* w_ih  = (const float*)d_in[8];
    const float* w_hh  = (const float*)d_in[9];
    const float* b_ih  = (const float*)d_in[10];
    const float* b_hh  = (const float*)d_in[11];
    const float* w_q   = (const float*)d_in[12];
    const float* b_q   = (const float*)d_in[13];
    const float* w_k   = (const float*)d_in[14];
    const float* b_k   = (const float*)d_in[15];
    const float* w_ba  = (const float*)d_in[16];
    const float* b_ba  = (const float*)d_in[17];
    const float* w_at  = (const float*)d_in[18];
    const float* b_at  = (const float*)d_in[19];
    const float* w_p1  = (const float*)d_in[20];
    const float* b_p1  = (const float*)d_in[21];
    const float* w_p2  = (const float*)d_in[22];
    const float* b_p2  = (const float*)d_in[23];
    const float* w_p   = (const float*)d_in[24];
    const float* b_p   = (const float*)d_in[25];
    const float* w_v1  = (const float*)d_in[26];
    const float* b_v1  = (const float*)d_in[27];
    const float* w_v2  = (const float*)d_in[28];
    const float* b_v2  = (const float*)d_in[29];
    const float* w_v   = (const float*)d_in[30];
    const float* b_v   = (const float*)d_in[31];

    const int B = in_sizes[0] / 256;  // 32768

    float* F = nullptr;
    cudaGetSymbolAddress((void**)&F, g_f32);
    __half* HF = nullptr;
    cudaGetSymbolAddress((void**)&HF, g_hf);

    float* tab   = F + F_TAB;
    float* pre2  = F + F_PRE2;

    float* out   = (float*)d_out;
    float* o_val = out;
    float* o_pol = out + (size_t)B;
    float* o_hx  = out + (size_t)B * 4;
    float* o_cx  = o_hx + (size_t)B * 256;

    // smem: 3 stages; stage = 18432 + BN*144
    const int SM128 = 3 * (18432 + 128 * 144);  // 110592
    const int SM96  = 3 * (18432 + 96 * 144);   // 96768
    const int SM64  = 3 * (18432 + 64 * 144);   // 82944
    cudaFuncSetAttribute(mma_gemm<128, 0, 5, 1>, cudaFuncAttributeMaxDynamicSharedMemorySize, SM128);
    cudaFuncSetAttribute(mma_gemm<128, 1, 0, 2>, cudaFuncAttributeMaxDynamicSharedMemorySize, SM128);
    cudaFuncSetAttribute(mma_gemm<128, 1, 2, 2>, cudaFuncAttributeMaxDynamicSharedMemorySize, SM128);
    cudaFuncSetAttribute(mma_gemm<64, 1, 0, 2>,  cudaFuncAttributeMaxDynamicSharedMemorySize, SM64);
    cudaFuncSetAttribute(mma_gemm<96, 1, 4, 0>,  cudaFuncAttributeMaxDynamicSharedMemorySize, SM96);

    // K0: tables
    k0_tables<<<1, 1024>>>(emb, w_ta, b_ta, w_ih, b_ih, b_hh, tab, pre2);

    // fused weight convert (9 segments, one launch)
    {
        WAll d;
        auto seg = [&](int i, const float* src, int srcld, int cols, int rows, int padrows,
                       size_t hoff) {
            d.s[i] = WSeg{src, nullptr, srcld, cols, rows, padrows * cols, 0, (long long)hoff};
        };
        seg(0, w_ih, 512, 256, 1024, 1024, H_WIH);
        seg(1, w_hh, 256, 256, 1024, 1024, H_WHH);
        seg(2, w_ba, 512, 512, 512, 512, H_WBA);
        seg(3, w_q,  256, 256, 256, 256, H_WQ);
        seg(4, w_k,  256, 256, 256, 256, H_WK);
        seg(5, w_at, 512, 512, 256, 256, H_WAT);
        seg(6, w_p1, 256, 256, 128, 128, H_WPV);
        seg(7, w_v1, 256, 256, 64, 64, H_WPV + 128 * 256);
        d.s[8] = WSeg{w_p2, w_v2, 0, 0, 0, 128 * 192, 2, (long long)H_WC};
        int total = 0;
        for (int i = 0; i < 9; i++) total += d.s[i].total;
        k_wsplit_all<<<(total + 255) / 256, 256>>>(d, HF);
    }

    // fused prep
    k_prep<<<(3 * B * 64 + 255) / 256, 256>>>(
        (const float4*)img, idx, tab, (const float4*)hx_in, (const float4*)query,
        HF + H_FUS, HF + H_HXI, HF + H_QRY, B * 64);

    // K2+K5 merged: gates GEMM (x<8, fp16 out) + qout GEMM (x>=8, fp16 out)
    mma_gemm<128, 0, 5, 1><<<dim3(10, B / 128), 256, SM128>>>(
        1024,
        HF + H_FUS, 256, HF + H_WIH, 256, 256,
        HF + H_HXI, 256, HF + H_WHH, 256, 256,
        nullptr, nullptr, 1 << 30, nullptr, nullptr, pre2, idx,
        nullptr, HF + H_GATES, 1024,
        HF + H_QRY, 256, HF + H_WQ, 256, 256, b_q, HF + H_QOUT, 256, 8,
        nullptr, nullptr, nullptr, nullptr, nullptr, nullptr);

    // K3: LSTM (fp16 gates)
    k_lstm<<<(B * 64 + 255) / 256, 256>>>(HF + H_GATES, cx_in, o_hx, o_cx, HF + H_HXO, B * 64);

    // K4: mlp = relu([fus|hx] @ w_ba^T + b_ba)  (fp16 only)
    mma_gemm<128, 1, 0, 2><<<dim3(4, B / 128), 256, SM128>>>(
        512,
        HF + H_FUS, 256, HF + H_WBA, 512, 256,
        HF + H_HXO, 256, HF + H_WBA + 256, 512, 256,
        b_ba, nullptr, 1 << 30, nullptr, nullptr, nullptr, nullptr, nullptr, HF + H_MLP, 512,
        nullptr, 0, nullptr, 0, 0, nullptr, nullptr, 0, 0,
        nullptr, nullptr, nullptr, nullptr, nullptr, nullptr);

    // K6: avec = tanh(qout_h + relu(key @ w_k^T + b_k)) * mlp_h[.,256+n]  (fp16)
    mma_gemm<128, 1, 2, 2><<<dim3(2, B / 128), 256, SM128>>>(
        256,
        HF + H_MLP, 512, HF + H_WK, 256, 256,
        nullptr, 0, nullptr, 0, 0,
        b_k, nullptr, 1 << 30, HF + H_QOUT, HF + H_MLP, nullptr, nullptr,
        nullptr, HF + H_AVEC, 256,
        nullptr, 0, nullptr, 0, 0, nullptr, nullptr, 0, 0,
        nullptr, nullptr, nullptr, nullptr, nullptr, nullptr);

    // K7: attnw = relu([avec|hx] @ w_at^T + b_at)  (fp16)
    mma_gemm<128, 1, 0, 2><<<dim3(2, B / 128), 256, SM128>>>(
        256,
        HF + H_AVEC, 256, HF + H_WAT, 512, 256,
        HF + H_HXO, 256, HF + H_WAT + 256, 512, 256,
        b_at, nullptr, 1 << 30, nullptr, nullptr, nullptr, nullptr, nullptr, HF + H_ATT, 256,
        nullptr, 0, nullptr, 0, 0, nullptr, nullptr, 0, 0,
        nullptr, nullptr, nullptr, nullptr, nullptr, nullptr);

    // K8: [pol1|val1] = relu(attnw @ [w_p1;w_v1]^T + [b_p1;b_v1])  N=192 (fp16)
    mma_gemm<64, 1, 0, 2><<<dim3(3, B / 128), 256, SM64>>>(
        192,
        HF + H_ATT, 256, HF + H_WPV, 256, 256,
        nullptr, 0, nullptr, 0, 0,
        b_p1, b_v1, 128, nullptr, nullptr, nullptr, nullptr, nullptr, HF + H_P1V1, 192,
        nullptr, 0, nullptr, 0, 0, nullptr, nullptr, 0, 0,
        nullptr, nullptr, nullptr, nullptr, nullptr, nullptr);

    // K9 fused with heads: [pol2|val2] GEMM (N=96, blockdiag) -> pol/val outputs
    mma_gemm<96, 1, 4, 0><<<dim3(1, B / 128), 256, SM96>>>(
        96,
        HF + H_P1V1, 192, HF + H_WC, 192, 192,
        nullptr, 0, nullptr, 0, 0,
        b_p2, b_v2, 64, nullptr, nullptr, nullptr, nullptr, nullptr, nullptr, 96,
        nullptr, 0, nullptr, 0, 0, nullptr, nullptr, 0, 0,
        w_p, b_p, w_v, b_v, o_val, o_pol);
}

// round 17
// speedup vs baseline: 1.1537x; 1.0119x over previous
#include <cuda_runtime.h>
#include <cuda_fp16.h>
#include <cstdint>
#include <math.h>

// ---------------------------------------------------------------------------
// Actor_Critic — single-pass fp16 MMA pipeline.
// 256-thread GEMM CTAs, K64 chunks, 3-stage cp.async ring, one barrier/chunk,
// 2 CTAs/SM, warp K-phase stagger, deferred c+2 prefetch (after first k16).
// qout merged into gates launch; gates fp16; K9 GEMM fused with final heads.
// ---------------------------------------------------------------------------

constexpr size_t S_B = 32768;

// fp32 scratch
constexpr size_t F_TAB   = 0;
constexpr size_t F_PRE2  = 1024;
constexpr size_t F_END   = F_PRE2 + 4096;
__device__ float g_f32[F_END];

// fp16 scratch
constexpr size_t H_WIH   = 0;                        // 1024x256
constexpr size_t H_WHH   = H_WIH   + 262144;         // 1024x256
constexpr size_t H_WBA   = H_WHH   + 262144;         // 512x512
constexpr size_t H_WQ    = H_WBA   + 262144;         // 256x256
constexpr size_t H_WK    = H_WQ    + 65536;          // 256x256
constexpr size_t H_WAT   = H_WK    + 65536;          // 256x512
constexpr size_t H_WPV   = H_WAT   + 131072;         // 192x256
constexpr size_t H_WC    = H_WPV   + 49152;          // 128x192 block-diag
constexpr size_t H_FUS   = H_WC    + 24576;          // B*256
constexpr size_t H_HXI   = H_FUS   + S_B * 256;
constexpr size_t H_QRY   = H_HXI   + S_B * 256;
constexpr size_t H_HXO   = H_QRY   + S_B * 256;
constexpr size_t H_MLP   = H_HXO   + S_B * 256;      // B*512
constexpr size_t H_AVEC  = H_MLP   + S_B * 512;
constexpr size_t H_ATT   = H_AVEC  + S_B * 256;
constexpr size_t H_P1V1  = H_ATT   + S_B * 256;      // B*192
constexpr size_t H_QOUT  = H_P1V1  + S_B * 192;      // B*256 (fp16 qout)
constexpr size_t H_GATES = H_QOUT  + S_B * 256;      // B*1024 (fp16 gates)
constexpr size_t H_END   = H_GATES + S_B * 1024;
__device__ __half g_hf[H_END];

__device__ __forceinline__ float sigmoidf_(float x) { return 1.f / (1.f + expf(-x)); }
__device__ __forceinline__ uint32_t pack2h(__half a, __half b) {
    return (uint32_t)__half_as_ushort(a) | ((uint32_t)__half_as_ushort(b) << 16);
}

// ---------------------------------------------------------------------------
// K0: gated_att table (4x256) + pre2 table (4x1024)
// ---------------------------------------------------------------------------
__global__ void k0_tables(const float* __restrict__ emb,  const float* __restrict__ w_ta,
                          const float* __restrict__ b_ta, const float* __restrict__ w_ih,
                          const float* __restrict__ b_ih, const float* __restrict__ b_hh,
                          float* __restrict__ tab, float* __restrict__ pre2) {
    int t = threadIdx.x;  // 1024
    {
        int r = t >> 8, j = t & 255;
        float s = b_ta[j];
        #pragma unroll
        for (int k = 0; k < 25; k++) s += emb[r * 25 + k] * w_ta[j * 25 + k];
        tab[t] = sigmoidf_(s);
    }
    __syncthreads();
    {
        int j = t;
        const float* wrow = &w_ih[(size_t)j * 512 + 256];
        float base = b_ih[j] + b_hh[j];
        for (int r = 0; r < 4; r++) {
            const float* tr = &tab[r * 256];
            float s = base;
            for (int k = 0; k < 256; k++) s += tr[k] * wrow[k];
            pre2[r * 1024 + j] = s;
        }
    }
}

// ---------------------------------------------------------------------------
// fused weight convert to fp16. mode 0: normal; mode 2: p2/v2 block-diag.
// ---------------------------------------------------------------------------
struct WSeg { const float* src; const float* src2; int srcld, cols, rows, total, mode;
              long long hoff; };
struct WAll { WSeg s[9]; };

__global__ void k_wsplit_all(WAll d, __half* __restrict__ base) {
    int i = blockIdx.x * blockDim.x + threadIdx.x;
    #pragma unroll
    for (int s = 0; s < 9; s++) {
        const WSeg& g = d.s[s];
        if (i < g.total) {
            float v;
            if (g.mode == 0) {
                int r = i / g.cols, c = i - r * g.cols;
                v = (r < g.rows) ? g.src[(size_t)r * g.srcld + c] : 0.f;
            } else {
                int r = i / 192, c = i - r * 192;
                if (r < 64)       v = (c < 128) ? g.src[r * 128 + c] : 0.f;
                else if (c >= 128 && r - 64 < 32) v = g.src2[(r - 64) * 64 + (c - 128)];
                else              v = 0.f;
            }
            base[g.hoff + i] = __float2half(v);
            return;
        }
        i -= g.total;
    }
}

// ---------------------------------------------------------------------------
// fused prep: region 0 fusion(img*tab[idx]); 1: round hx_in; 2: round query
// ---------------------------------------------------------------------------
__global__ void k_prep(const float4* __restrict__ img, const int* __restrict__ idx,
                       const float* __restrict__ tab,
                       const float4* __restrict__ hx_in, const float4* __restrict__ query,
                       __half* __restrict__ fus, __half* __restrict__ hxi,
                       __half* __restrict__ qry, int nq) {
    int i = blockIdx.x * blockDim.x + threadIdx.x;
    int reg = 0;
    if (i >= nq) { i -= nq; reg = 1; }
    if (i >= nq) { i -= nq; reg = 2; }
    if (i >= nq) return;
    float4 v;
    __half* dst;
    if (reg == 0) {
        int b = i >> 6, j4 = (i & 63) << 2;
        float4 g = *reinterpret_cast<const float4*>(tab + idx[b] * 256 + j4);
        v = img[i];
        v.x *= g.x; v.y *= g.y; v.z *= g.z; v.w *= g.w;
        dst = fus;
    } else if (reg == 1) { v = hx_in[i]; dst = hxi; }
    else                 { v = query[i]; dst = qry; }
    uint2 u = make_uint2(pack2h(__float2half(v.x), __float2half(v.y)),
                         pack2h(__float2half(v.z), __float2half(v.w)));
    *reinterpret_cast<uint2*>(dst + (size_t)i * 4) = u;
}

// ---------------------------------------------------------------------------
// K3: LSTM (fp16 gates in) -> hx,cx fp32 (outputs) + hx fp16. 8 units/thread.
// total8 = B*32
// ---------------------------------------------------------------------------
__global__ void k_lstm(const __half* __restrict__ gates, const float* __restrict__ cx_in,
                       float* __restrict__ hx_out, float* __restrict__ cx_out,
                       __half* __restrict__ hxo, int total8) {
    int i = blockIdx.x * blockDim.x + threadIdx.x;
    if (i >= total8) return;
    int b = i >> 5, j = (i & 31) << 3;
    const __half* g = gates + (size_t)b * 1024 + j;
    uint4 ui = *reinterpret_cast<const uint4*>(g);
    uint4 uf = *reinterpret_cast<const uint4*>(g + 256);
    uint4 ug = *reinterpret_cast<const uint4*>(g + 512);
    uint4 uo = *reinterpret_cast<const uint4*>(g + 768);
    size_t o = (size_t)b * 256 + j;
    float4 c0a = *reinterpret_cast<const float4*>(cx_in + o);
    float4 c0b = *reinterpret_cast<const float4*>(cx_in + o + 4);
    float gi[8], gf[8], gg[8], go[8];
    auto up = [](uint4 u, float* f) {
        const uint32_t w[4] = {u.x, u.y, u.z, u.w};
        #pragma unroll
        for (int q = 0; q < 4; q++) {
            __half2 h = *reinterpret_cast<const __half2*>(&w[q]);
            f[2 * q]     = __low2float(h);
            f[2 * q + 1] = __high2float(h);
        }
    };
    up(ui, gi); up(uf, gf); up(ug, gg); up(uo, go);
    const float c0[8] = {c0a.x, c0a.y, c0a.z, c0a.w, c0b.x, c0b.y, c0b.z, c0b.w};
    float ho[8], co[8];
    #pragma unroll
    for (int q = 0; q < 8; q++) {
        float c = sigmoidf_(gf[q]) * c0[q] + sigmoidf_(gi[q]) * tanhf(gg[q]);
        co[q] = c;
        ho[q] = sigmoidf_(go[q]) * tanhf(c);
    }
    *reinterpret_cast<float4*>(hx_out + o)     = make_float4(ho[0], ho[1], ho[2], ho[3]);
    *reinterpret_cast<float4*>(hx_out + o + 4) = make_float4(ho[4], ho[5], ho[6], ho[7]);
    *reinterpret_cast<float4*>(cx_out + o)     = make_float4(co[0], co[1], co[2], co[3]);
    *reinterpret_cast<float4*>(cx_out + o + 4) = make_float4(co[4], co[5], co[6], co[7]);
    uint4 u = make_uint4(pack2h(__float2half(ho[0]), __float2half(ho[1])),
                         pack2h(__float2half(ho[2]), __float2half(ho[3])),
                         pack2h(__float2half(ho[4]), __float2half(ho[5])),
                         pack2h(__float2half(ho[6]), __float2half(ho[7])));
    *reinterpret_cast<uint4*>(hxo + o) = u;
}

// ---------------------------------------------------------------------------
// MMA / cp.async helpers
// ---------------------------------------------------------------------------
__device__ __forceinline__ void ldm4(uint32_t* r, uint32_t addr) {
    asm volatile("ldmatrix.sync.aligned.m8n8.x4.shared.b16 {%0,%1,%2,%3}, [%4];"
                 : "=r"(r[0]), "=r"(r[1]), "=r"(r[2]), "=r"(r[3]) : "r"(addr));
}
__device__ __forceinline__ void mma16816(float* c, const uint32_t* a, uint32_t b0, uint32_t b1) {
    asm volatile(
        "mma.sync.aligned.m16n8k16.row.col.f32.f16.f16.f32 "
        "{%0,%1,%2,%3}, {%4,%5,%6,%7}, {%8,%9}, {%0,%1,%2,%3};"
        : "+f"(c[0]), "+f"(c[1]), "+f"(c[2]), "+f"(c[3])
        : "r"(a[0]), "r"(a[1]), "r"(a[2]), "r"(a[3]), "r"(b0), "r"(b1));
}
#define CPA16(dst, src) asm volatile("cp.async.cg.shared.global [%0], [%1], 16;\n" :: "r"(dst), "l"(src))
#define CPCOMMIT()      asm volatile("cp.async.commit_group;\n")
#define CPWAIT1()       asm volatile("cp.async.wait_group 1;\n")
#define CPWAIT0()       asm volatile("cp.async.wait_group 0;\n")

// ---------------------------------------------------------------------------
// GEMM: C = epi( sum_seg A_seg @ W_seg^T ), fp16 single pass, fp32 acc.
// 256 threads, 8 warps (4m x 2n), BM=128, K64 chunks (144B rows), 3-stage
// cp.async ring, one barrier/chunk, warp K-phase stagger, deferred prefetch.
// EPI 0: +bias (split at nsplit), relu if ACT
// EPI 2: (+bias, relu) -> tanh(qout_h + v) * mlp_h[.,256+n]   (fp16 aux)
// EPI 4: (+bias split, relu) -> stage smem -> fused heads (pol/val) direct out
// EPI 5: dual-job: blockIdx.x < gx1 -> gates (+pre2 via idxp, fp16 Ch);
//        else qout job (Aq,Wq,Kq, +biasq, relu, fp16 Cqh)
// OUTM bit0: fp32 C; bit1: fp16 Ch.
// ---------------------------------------------------------------------------
template <int BN, int ACT, int EPI, int OUTM>
__global__ void __launch_bounds__(256, 2)
mma_gemm(int N,
         const __half* __restrict__ A0, int lda0,
         const __half* __restrict__ W0, int ldw0, int K0,
         const __half* __restrict__ A1, int lda1,
         const __half* __restrict__ W1, int ldw1, int K1,
         const float* __restrict__ bias, const float* __restrict__ bias2, int nsplit,
         const __half* __restrict__ auxh0, const __half* __restrict__ auxh1,
         const float* __restrict__ aux0,
         const int* __restrict__ idxp,
         float* __restrict__ C, __half* __restrict__ Ch, int ldc,
         const __half* __restrict__ Aq, int ldaq,
         const __half* __restrict__ Wq, int ldwq, int Kq,
         const float* __restrict__ biasq, __half* __restrict__ Cqh, int ldcq, int gx1,
         const float* __restrict__ hw_p, const float* __restrict__ hb_p,
         const float* __restrict__ hw_v, const float* __restrict__ hb_v,
         float* __restrict__ o_val, float* __restrict__ o_pol) {
    constexpr int WN      = BN / 2;                 // warp n-extent (2 warps in n)
    constexpr int NT8     = WN / 8;
    constexpr int N16T    = WN / 16;
    constexpr int SSTR    = 72;                     // halves/row: 64 data + 8 pad (144B)
    constexpr int A_BYTES = 128 * SSTR * 2;         // 18432
    constexpr int W_BYTES = BN * SSTR * 2;
    constexpr int STAGEB  = A_BYTES + W_BYTES;
    constexpr int WIT     = BN / 32;                // W cp.async iters

    extern __shared__ __half smem_dyn[];

    const int tid  = threadIdx.x;
    const int lane = tid & 31;
    const int wid  = tid >> 5;
    const int wm = wid & 3, wn = wid >> 2;          // 4 x 2 warps
    const int m0 = blockIdx.y * 128;

    const bool isq = (EPI == 5) && ((int)blockIdx.x >= gx1);
    const int n0 = (isq ? ((int)blockIdx.x - gx1) : (int)blockIdx.x) * BN;

    const __half* jA0 = isq ? Aq : A0;  const int jlda0 = isq ? ldaq : lda0;
    const __half* jW0 = isq ? Wq : W0;  const int jldw0 = isq ? ldwq : ldw0;
    const int jK0 = isq ? Kq : K0;
    const int jK1 = isq ? 0  : K1;

    const uint32_t smb = (uint32_t)__cvta_generic_to_shared(smem_dyn);

    float acc[2][NT8][4];
    #pragma unroll
    for (int i = 0; i < 2; i++)
        #pragma unroll
        for (int j = 0; j < NT8; j++)
            #pragma unroll
            for (int q = 0; q < 4; q++) acc[i][j][q] = 0.f;

    const int nc0 = jK0 >> 6;
    const int NC  = nc0 + (jK1 >> 6);

    auto issue = [&](int c) {
        const __half *A, *W;
        int lda, ldw, kc;
        if (c < nc0) { A = jA0; W = jW0; lda = jlda0; ldw = jldw0; kc = c << 6; }
        else         { A = A1;  W = W1;  lda = lda1;  ldw = ldw1;  kc = (c - nc0) << 6; }
        const uint32_t sb = smb + (uint32_t)(c % 3) * STAGEB;
        #pragma unroll
        for (int it = 0; it < 4; it++) {            // A: 128 rows x 8 segs
            int idx = tid + it * 256;
            int row = idx >> 3, seg = idx & 7;
            uint32_t off = (uint32_t)(row * SSTR + seg * 8) * 2;
            CPA16(sb + off, A + (size_t)(m0 + row) * lda + kc + seg * 8);
        }
        #pragma unroll
        for (int it = 0; it < WIT; it++) {          // W: BN rows x 8 segs
            int idx = tid + it * 256;
            int row = idx >> 3, seg = idx & 7;
            uint32_t off = (uint32_t)(row * SSTR + seg * 8) * 2;
            CPA16(sb + A_BYTES + off, W + (size_t)(n0 + row) * ldw + kc + seg * 8);
        }
    };

    issue(0); CPCOMMIT();
    if (NC > 1) { issue(1); CPCOMMIT(); }

    for (int c = 0; c < NC; c++) {
        if (c + 1 < NC) CPWAIT1(); else CPWAIT0();
        __syncthreads();

        const uint32_t sb = smb + (uint32_t)(c % 3) * STAGEB;
        const uint32_t bA = sb;
        const uint32_t bW = sb + A_BYTES;

        // K-phase stagger (per-warp start slot) + deferred c+2 prefetch after
        // the first k16 so MMAs begin immediately post-barrier.
        #pragma unroll
        for (int kt = 0; kt < 4; kt++) {
            const int kk = (((kt + wid) & 3) << 4);
            const int col = kk + ((lane >> 4) << 3);
            uint32_t a0[4], a1[4];
            {
                int row = wm * 32 + (lane & 15);
                ldm4(a0, bA + (uint32_t)(row * SSTR + col) * 2u);
                ldm4(a1, bA + (uint32_t)((row + 16) * SSTR + col) * 2u);
            }
            #pragma unroll
            for (int t = 0; t < N16T; t++) {
                uint32_t bh[4];
                int row = wn * WN + t * 16 + (lane & 15);
                ldm4(bh, bW + (uint32_t)(row * SSTR + col) * 2u);
                #pragma unroll
                for (int hs = 0; hs < 2; hs++) {
                    int nt = 2 * t + hs;
                    mma16816(acc[0][nt], a0, bh[hs], bh[2 + hs]);
                    mma16816(acc[1][nt], a1, bh[hs], bh[2 + hs]);
                }
            }
            if (kt == 0 && c + 2 < NC) { issue(c + 2); CPCOMMIT(); }
        }
    }

    if (EPI == 5) {
        #pragma unroll
        for (int mt = 0; mt < 2; mt++) {
            int r0 = m0 + wm * 32 + mt * 16 + (lane >> 2);
            int r1 = r0 + 8;
            int ib0 = 0, ib1 = 0;
            if (!isq) { ib0 = idxp[r0]; ib1 = idxp[r1]; }
            #pragma unroll
            for (int nt = 0; nt < NT8; nt++) {
                int cc = n0 + wn * WN + nt * 8 + ((lane & 3) << 1);
                #pragma unroll
                for (int p = 0; p < 2; p++) {
                    int r  = p ? r1 : r0;
                    float x = acc[mt][nt][2 * p];
                    float y = acc[mt][nt][2 * p + 1];
                    if (isq) {
                        x = fmaxf(x + biasq[cc], 0.f);
                        y = fmaxf(y + biasq[cc + 1], 0.f);
                        *reinterpret_cast<uint32_t*>(&Cqh[(size_t)r * ldcq + cc]) =
                            pack2h(__float2half(x), __float2half(y));
                    } else {
                        int ib = p ? ib1 : ib0;
                        float2 pv = *reinterpret_cast<const float2*>(&aux0[(size_t)ib * 1024 + cc]);
                        x += pv.x;
                        y += pv.y;
                        *reinterpret_cast<uint32_t*>(&Ch[(size_t)r * ldc + cc]) =
                            pack2h(__float2half(x), __float2half(y));
                    }
                }
            }
        }
        return;
    }

    if (EPI == 4) {
        // ---- fused pol2/val2 + heads epilogue (n0 == 0, N == 96) ----
        __syncthreads();                            // pipeline smem reusable
        float* sf = reinterpret_cast<float*>(smem_dyn);   // stride 98 floats
        #pragma unroll
        for (int mt = 0; mt < 2; mt++) {
            int rl0 = wm * 32 + mt * 16 + (lane >> 2);
            #pragma unroll
            for (int nt = 0; nt < NT8; nt++) {
                int cc = wn * WN + nt * 8 + ((lane & 3) << 1);
                float bb0 = (cc < nsplit) ? bias[cc] : bias2[cc - nsplit];
                float bb1 = (cc < nsplit) ? bias[cc + 1] : bias2[cc + 1 - nsplit];
                #pragma unroll
                for (int p = 0; p < 2; p++) {
                    int rl = rl0 + p * 8;
                    float x = fmaxf(acc[mt][nt][2 * p] + bb0, 0.f);
                    float y = fmaxf(acc[mt][nt][2 * p + 1] + bb1, 0.f);
                    *reinterpret_cast<float2*>(&sf[rl * 98 + cc]) = make_float2(x, y);
                }
            }
        }
        __syncthreads();
        if (tid < 128) {
            int b = m0 + tid;
            const float* row = &sf[tid * 98];
            float p0 = hb_p[0], p1 = hb_p[1], p2 = hb_p[2];
            #pragma unroll
            for (int k = 0; k < 64; k++) {
                float xv = row[k];
                p0 = fmaf(xv, hw_p[k], p0);
                p1 = fmaf(xv, hw_p[64 + k], p1);
                p2 = fmaf(xv, hw_p[128 + k], p2);
            }
            o_pol[(size_t)b * 3 + 0] = p0;
            o_pol[(size_t)b * 3 + 1] = p1;
            o_pol[(size_t)b * 3 + 2] = p2;
            float v = hb_v[0];
            #pragma unroll
            for (int k = 0; k < 32; k++) v = fmaf(row[64 + k], hw_v[k], v);
            o_val[b] = v;
        }
        return;
    }

    // ---- standard epilogue (EPI 0 / 2) ----
    #pragma unroll
    for (int mt = 0; mt < 2; mt++) {
        int r0 = m0 + wm * 32 + mt * 16 + (lane >> 2);
        int r1 = r0 + 8;
        #pragma unroll
        for (int nt = 0; nt < NT8; nt++) {
            int cc = n0 + wn * WN + nt * 8 + ((lane & 3) << 1);
            if (cc < N) {
                float bb0 = 0.f, bb1 = 0.f;
                if (bias) {
                    if (cc < nsplit) { bb0 = bias[cc]; bb1 = bias[cc + 1]; }
                    else             { bb0 = bias2[cc - nsplit]; bb1 = bias2[cc + 1 - nsplit]; }
                }
                #pragma unroll
                for (int p = 0; p < 2; p++) {
                    int r = p ? r1 : r0;
                    float x = acc[mt][nt][2 * p] + bb0;
                    float y = acc[mt][nt][2 * p + 1] + bb1;
                    if (ACT) { x = fmaxf(x, 0.f); y = fmaxf(y, 0.f); }
                    if (EPI == 2) {
                        __half2 q2 = *reinterpret_cast<const __half2*>(&auxh0[(size_t)r * 256 + cc]);
                        __half2 v2 = *reinterpret_cast<const __half2*>(&auxh1[(size_t)r * 512 + 256 + cc]);
                        x = tanhf(__low2float(q2) + x)  * __low2float(v2);
                        y = tanhf(__high2float(q2) + y) * __high2float(v2);
                    }
                    size_t o = (size_t)r * ldc + cc;
                    if (OUTM & 1)
                        *reinterpret_cast<float2*>(&C[o]) = make_float2(x, y);
                    if (OUTM & 2)
                        *reinterpret_cast<uint32_t*>(Ch + o) = pack2h(__float2half(x), __float2half(y));
                }
            }
        }
    }
}

// ---------------------------------------------------------------------------
// host launcher
// ---------------------------------------------------------------------------
extern "C" void kernel_launch(void* const* d_in, const int* in_sizes, int n_in,
                              void* d_out, int out_size) {
    const float* img   = (const float*)d_in[0];
    const int*   idx   = (const int*)  d_in[1];
    const float* hx_in = (const float*)d_in[2];
    const float* cx_in = (const float*)d_in[3];
    const float* query = (const float*)d_in[4];
    const float* emb   = (const float*)d_in[5];
    const float* w_ta  = (const float*)d_in[6];
    const float* b_ta  = (const float*)d_in[7];
    const float* w_ih  = (const float*)d_in[8];
    const float* w_hh  = (const float*)d_in[9];
    const float* b_ih  = (const float*)d_in[10];
    const float* b_hh  = (const float*)d_in[11];
    const float* w_q   = (const float*)d_in[12];
    const float* b_q   = (const float*)d_in[13];
    const float* w_k   = (const float*)d_in[14];
    const float* b_k   = (const float*)d_in[15];
    const float* w_ba  = (const float*)d_in[16];
    const float* b_ba  = (const float*)d_in[17];
    const float* w_at  = (const float*)d_in[18];
    const float* b_at  = (const float*)d_in[19];
    const float* w_p1  = (const float*)d_in[20];
    const float* b_p1  = (const float*)d_in[21];
    const float* w_p2  = (const float*)d_in[22];
    const float* b_p2  = (const float*)d_in[23];
    const float* w_p   = (const float*)d_in[24];
    const float* b_p   = (const float*)d_in[25];
    const float* w_v1  = (const float*)d_in[26];
    const float* b_v1  = (const float*)d_in[27];
    const float* w_v2  = (const float*)d_in[28];
    const float* b_v2  = (const float*)d_in[29];
    const float* w_v   = (const float*)d_in[30];
    const float* b_v   = (const float*)d_in[31];

    const int B = in_sizes[0] / 256;  // 32768

    float* F = nullptr;
    cudaGetSymbolAddress((void**)&F, g_f32);
    __half* HF = nullptr;
    cudaGetSymbolAddress((void**)&HF, g_hf);

    float* tab   = F + F_TAB;
    float* pre2  = F + F_PRE2;

    float* out   = (float*)d_out;
    float* o_val = out;
    float* o_pol = out + (size_t)B;
    float* o_hx  = out + (size_t)B * 4;
    float* o_cx  = o_hx + (size_t)B * 256;

    // smem: 3 stages; stage = 18432 + BN*144
    const int SM128 = 3 * (18432 + 128 * 144);  // 110592
    const int SM96  = 3 * (18432 + 96 * 144);   // 96768
    const int SM64  = 3 * (18432 + 64 * 144);   // 82944
    cudaFuncSetAttribute(mma_gemm<128, 0, 5, 1>, cudaFuncAttributeMaxDynamicSharedMemorySize, SM128);
    cudaFuncSetAttribute(mma_gemm<128, 1, 0, 2>, cudaFuncAttributeMaxDynamicSharedMemorySize, SM128);
    cudaFuncSetAttribute(mma_gemm<128, 1, 2, 2>, cudaFuncAttributeMaxDynamicSharedMemorySize, SM128);
    cudaFuncSetAttribute(mma_gemm<64, 1, 0, 2>,  cudaFuncAttributeMaxDynamicSharedMemorySize, SM64);
    cudaFuncSetAttribute(mma_gemm<96, 1, 4, 0>,  cudaFuncAttributeMaxDynamicSharedMemorySize, SM96);

    // K0: tables
    k0_tables<<<1, 1024>>>(emb, w_ta, b_ta, w_ih, b_ih, b_hh, tab, pre2);

    // fused weight convert (9 segments, one launch)
    {
        WAll d;
        auto seg = [&](int i, const float* src, int srcld, int cols, int rows, int padrows,
                       size_t hoff) {
            d.s[i] = WSeg{src, nullptr, srcld, cols, rows, padrows * cols, 0, (long long)hoff};
        };
        seg(0, w_ih, 512, 256, 1024, 1024, H_WIH);
        seg(1, w_hh, 256, 256, 1024, 1024, H_WHH);
        seg(2, w_ba, 512, 512, 512, 512, H_WBA);
        seg(3, w_q,  256, 256, 256, 256, H_WQ);
        seg(4, w_k,  256, 256, 256, 256, H_WK);
        seg(5, w_at, 512, 512, 256, 256, H_WAT);
        seg(6, w_p1, 256, 256, 128, 128, H_WPV);
        seg(7, w_v1, 256, 256, 64, 64, H_WPV + 128 * 256);
        d.s[8] = WSeg{w_p2, w_v2, 0, 0, 0, 128 * 192, 2, (long long)H_WC};
        int total = 0;
        for (int i = 0; i < 9; i++) total += d.s[i].total;
        k_wsplit_all<<<(total + 255) / 256, 256>>>(d, HF);
    }

    // fused prep
    k_prep<<<(3 * B * 64 + 255) / 256, 256>>>(
        (const float4*)img, idx, tab, (const float4*)hx_in, (const float4*)query,
        HF + H_FUS, HF + H_HXI, HF + H_QRY, B * 64);

    // K2+K5 merged: gates GEMM (x<8, fp16 out) + qout GEMM (x>=8, fp16 out)
    mma_gemm<128, 0, 5, 1><<<dim3(10, B / 128), 256, SM128>>>(
        1024,
        HF + H_FUS, 256, HF + H_WIH, 256, 256,
        HF + H_HXI, 256, HF + H_WHH, 256, 256,
        nullptr, nullptr, 1 << 30, nullptr, nullptr, pre2, idx,
        nullptr, HF + H_GATES, 1024,
        HF + H_QRY, 256, HF + H_WQ, 256, 256, b_q, HF + H_QOUT, 256, 8,
        nullptr, nullptr, nullptr, nullptr, nullptr, nullptr);

    // K3: LSTM (fp16 gates, 8-wide)
    k_lstm<<<(B * 32 + 255) / 256, 256>>>(HF + H_GATES, cx_in, o_hx, o_cx, HF + H_HXO, B * 32);

    // K4: mlp = relu([fus|hx] @ w_ba^T + b_ba)  (fp16 only)
    mma_gemm<128, 1, 0, 2><<<dim3(4, B / 128), 256, SM128>>>(
        512,
        HF + H_FUS, 256, HF + H_WBA, 512, 256,
        HF + H_HXO, 256, HF + H_WBA + 256, 512, 256,
        b_ba, nullptr, 1 << 30, nullptr, nullptr, nullptr, nullptr, nullptr, HF + H_MLP, 512,
        nullptr, 0, nullptr, 0, 0, nullptr, nullptr, 0, 0,
        nullptr, nullptr, nullptr, nullptr, nullptr, nullptr);

    // K6: avec = tanh(qout_h + relu(key @ w_k^T + b_k)) * mlp_h[.,256+n]  (fp16)
    mma_gemm<128, 1, 2, 2><<<dim3(2, B / 128), 256, SM128>>>(
        256,
        HF + H_MLP, 512, HF + H_WK, 256, 256,
        nullptr, 0, nullptr, 0, 0,
        b_k, nullptr, 1 << 30, HF + H_QOUT, HF + H_MLP, nullptr, nullptr,
        nullptr, HF + H_AVEC, 256,
        nullptr, 0, nullptr, 0, 0, nullptr, nullptr, 0, 0,
        nullptr, nullptr, nullptr, nullptr, nullptr, nullptr);

    // K7: attnw = relu([avec|hx] @ w_at^T + b_at)  (fp16)
    mma_gemm<128, 1, 0, 2><<<dim3(2, B / 128), 256, SM128>>>(
        256,
        HF + H_AVEC, 256, HF + H_WAT, 512, 256,
        HF + H_HXO, 256, HF + H_WAT + 256, 512, 256,
        b_at, nullptr, 1 << 30, nullptr, nullptr, nullptr, nullptr, nullptr, HF + H_ATT, 256,
        nullptr, 0, nullptr, 0, 0, nullptr, nullptr, 0, 0,
        nullptr, nullptr, nullptr, nullptr, nullptr, nullptr);

    // K8: [pol1|val1] = relu(attnw @ [w_p1;w_v1]^T + [b_p1;b_v1])  N=192 (fp16)
    mma_gemm<64, 1, 0, 2><<<dim3(3, B / 128), 256, SM64>>>(
        192,
        HF + H_ATT, 256, HF + H_WPV, 256, 256,
        nullptr, 0, nullptr, 0, 0,
        b_p1, b_v1, 128, nullptr, nullptr, nullptr, nullptr, nullptr, HF + H_P1V1, 192,
        nullptr, 0, nullptr, 0, 0, nullptr, nullptr, 0, 0,
        nullptr, nullptr, nullptr, nullptr, nullptr, nullptr);

    // K9 fused with heads: [pol2|val2] GEMM (N=96, blockdiag) -> pol/val outputs
    mma_gemm<96, 1, 4, 0><<<dim3(1, B / 128), 256, SM96>>>(
        96,
        HF + H_P1V1, 192, HF + H_WC, 192, 192,
        nullptr, 0, nullptr, 0, 0,
        b_p2, b_v2, 64, nullptr, nullptr, nullptr, nullptr, nullptr, nullptr, 96,
        nullptr, 0, nullptr, 0, 0, nullptr, nullptr, 0, 0,
        w_p, b_p, w_v, b_v, o_val, o_pol);
}